// round 8
// baseline (speedup 1.0000x reference)
#include <cuda_runtime.h>
#include <cuda_bf16.h>
#include <cstdint>
#include <cstddef>

// Problem constants (match reference)
#define N_NODES 50000
#define N_EDGES 800000
#define D_IN    128
#define D_HID   256
#define D_OUT   128

// ---------------------------------------------------------------------------
// Pipeline (8 GPU work items; capture slot 5 = gemm_x):
//   1 weight  : U packed for mma fragments (bf16 hi/lo), c, d
//   2 count   : dst histogram (inline idx-dtype detect)
//   3 scan    : rowoff/cursor/invdeg/flag; self-cleans g_cnt
//   4 fill    : CSR adjacency
//   5 gemm_x  : out  = x @ U3^T + c + flag*d
//   6 gather1 : m1[n] = invdeg[n] * sum x[s]
//   7 gather2 : A2[n] = invdeg[n] * sum m1[s]
//   8 gemm_acc: out += A2 @ U1^T + m1 @ U2^T
// ---------------------------------------------------------------------------

// Device scratch
__device__ int   g_cnt[N_NODES];          // zero at load; scan re-zeroes per replay
__device__ int   g_rowoff[N_NODES + 1];
__device__ int   g_cursor[N_NODES];
__device__ int   g_eadj[N_EDGES];
__device__ float g_invdeg[N_NODES];
__device__ float g_flag[N_NODES];
__device__ float g_m1[(size_t)N_NODES * 128];
__device__ float g_A2[(size_t)N_NODES * 128];
__device__ uint4 g_Upk[128 * 24 * 4];     // fragment-packed U (hi/lo)
__device__ float g_c[128];
__device__ float g_d[128];

// ---------------------------------------------------------------------------
// mma helpers
// ---------------------------------------------------------------------------
__device__ __forceinline__ void mma16816(float* d, const uint32_t* a, const uint32_t* b) {
    asm volatile(
        "mma.sync.aligned.m16n8k16.row.col.f32.bf16.bf16.f32 "
        "{%0,%1,%2,%3}, {%4,%5,%6,%7}, {%8,%9}, {%0,%1,%2,%3};"
        : "+f"(d[0]), "+f"(d[1]), "+f"(d[2]), "+f"(d[3])
        : "r"(a[0]), "r"(a[1]), "r"(a[2]), "r"(a[3]), "r"(b[0]), "r"(b[1]));
}
__device__ __forceinline__ void split2(float2 v, uint32_t& hi, uint32_t& lo) {
    __nv_bfloat162 h = __float22bfloat162_rn(v);
    float2 hv = __bfloat1622float2(h);
    __nv_bfloat162 l = __float22bfloat162_rn(make_float2(v.x - hv.x, v.y - hv.y));
    hi = *reinterpret_cast<uint32_t*>(&h);
    lo = *reinterpret_cast<uint32_t*>(&l);
}
__device__ __forceinline__ uint32_t packbf2(float a, float b) {
    __nv_bfloat162 h = __float22bfloat162_rn(make_float2(a, b));
    return *reinterpret_cast<uint32_t*>(&h);
}

// Per-block idx-dtype detection (int32 read as int64 -> >= 2^32 a.s.)
__device__ __forceinline__ int detect_idx64_block(const void* eidx) {
    __shared__ int s_idx64;
    if (threadIdx.x < 32) {
        const long long* p = (const long long*)eidx;
        int ok = 1;
        #pragma unroll
        for (int i = 0; i < 16; ++i) {
            long long v = p[threadIdx.x * 16 + i];
            ok &= (v >= 0 && v < (long long)N_NODES);
        }
        unsigned m = __ballot_sync(0xffffffffu, ok);
        if (threadIdx.x == 0) s_idx64 = (m == 0xffffffffu) ? 1 : 0;
    }
    __syncthreads();
    return s_idx64;
}

// ---------------------------------------------------------------------------
// Weights: U fragment-packed (hi/lo) + c, d.
// Upk[((n*24)+ktg)*4+tq] = {hi(k0,k0+1), hi(k0+8,k0+9), lo(...), lo(...)}
// k0 = (ktg%8)*16 + 2*tq, seg = ktg/8 -> U1/U2/U3.
// ---------------------------------------------------------------------------
__global__ __launch_bounds__(256)
void weight_kernel(const float* __restrict__ Wl1,
                   const float* __restrict__ Wr1,
                   const float* __restrict__ Wl2,
                   const float* __restrict__ Wr2,
                   const float* __restrict__ b1,
                   const float* __restrict__ b2) {
    const int tid = blockIdx.x * blockDim.x + threadIdx.x;

    if (tid < 128 * 96) {
        const int n   = tid / 96;
        const int rem = tid - n * 96;
        const int ktg = rem >> 2;
        const int tq  = rem & 3;
        const int seg = ktg >> 3;
        const int k0  = (ktg & 7) * 16 + 2 * tq;

        float u[4] = {0.f, 0.f, 0.f, 0.f};
        const float* A1 = Wl2 + (size_t)n * 256;
        const float* A2 = Wr2 + (size_t)n * 256;
        #pragma unroll 4
        for (int t = 0; t < 256; ++t) {
            const float wl2 = A1[t];
            const float wr2 = A2[t];
            const float* rl = Wl1 + (size_t)t * 128 + k0;
            const float* rr = Wr1 + (size_t)t * 128 + k0;
            if (seg == 0) {
                u[0] += wl2 * rl[0]; u[1] += wl2 * rl[1];
                u[2] += wl2 * rl[8]; u[3] += wl2 * rl[9];
            } else if (seg == 1) {
                u[0] += wl2 * rr[0] + wr2 * rl[0];
                u[1] += wl2 * rr[1] + wr2 * rl[1];
                u[2] += wl2 * rr[8] + wr2 * rl[8];
                u[3] += wl2 * rr[9] + wr2 * rl[9];
            } else {
                u[0] += wr2 * rr[0]; u[1] += wr2 * rr[1];
                u[2] += wr2 * rr[8]; u[3] += wr2 * rr[9];
            }
        }
        uint32_t h0 = packbf2(u[0], u[1]);
        uint32_t h1 = packbf2(u[2], u[3]);
        float r0 = u[0] - __bfloat162float(__ushort_as_bfloat16((uint16_t)(h0 & 0xffff)));
        float r1 = u[1] - __bfloat162float(__ushort_as_bfloat16((uint16_t)(h0 >> 16)));
        float r2 = u[2] - __bfloat162float(__ushort_as_bfloat16((uint16_t)(h1 & 0xffff)));
        float r3 = u[3] - __bfloat162float(__ushort_as_bfloat16((uint16_t)(h1 >> 16)));
        g_Upk[tid] = make_uint4(h0, h1, packbf2(r0, r1), packbf2(r2, r3));
    } else if (tid < 128 * 96 + 128) {
        const int a = tid - 128 * 96;
        float c = 0.f, d = 0.f;
        #pragma unroll 4
        for (int k = 0; k < 256; ++k) {
            c += Wr2[a * 256 + k] * b1[k];
            d += Wl2[a * 256 + k] * b1[k];
        }
        g_c[a] = b2[a] + c;
        g_d[a] = d;
    }
}

// ---------------------------------------------------------------------------
// CSR build
// ---------------------------------------------------------------------------
__global__ __launch_bounds__(256)
void count_kernel(const void* __restrict__ eidx) {
    const int idx64 = detect_idx64_block(eidx);
    const int e = blockIdx.x * blockDim.x + threadIdx.x;
    if (e >= N_EDGES) return;
    int dst;
    if (idx64) dst = (int)((const long long*)eidx)[N_EDGES + e];
    else       dst = ((const int*)eidx)[N_EDGES + e];
    atomicAdd(&g_cnt[dst], 1);
}

#define SCAN_T 1024
#define SCAN_CH 49
__global__ __launch_bounds__(SCAN_T)
void scan_kernel() {
    __shared__ int wsum[32];
    const int t = threadIdx.x;
    const int base = t * SCAN_CH;

    int cnt[SCAN_CH];
    int lsum = 0;
    #pragma unroll 7
    for (int i = 0; i < SCAN_CH; ++i) {
        const int idx = base + i;
        cnt[i] = (idx < N_NODES) ? g_cnt[idx] : 0;
        lsum += cnt[i];
    }

    int v = lsum;
    #pragma unroll
    for (int d = 1; d < 32; d <<= 1) {
        int n = __shfl_up_sync(0xffffffffu, v, d);
        if ((t & 31) >= d) v += n;
    }
    if ((t & 31) == 31) wsum[t >> 5] = v;
    __syncthreads();
    if (t < 32) {
        int w = wsum[t];
        #pragma unroll
        for (int d = 1; d < 32; d <<= 1) {
            int n = __shfl_up_sync(0xffffffffu, w, d);
            if (t >= d) w += n;
        }
        wsum[t] = w;
    }
    __syncthreads();
    int run = v + ((t >= 32) ? wsum[(t >> 5) - 1] : 0) - lsum;

    #pragma unroll 7
    for (int i = 0; i < SCAN_CH; ++i) {
        const int idx = base + i;
        if (idx < N_NODES) {
            const int c = cnt[i];
            g_rowoff[idx] = run;
            g_cursor[idx] = run;
            g_invdeg[idx] = 1.0f / fmaxf((float)c, 1.0f);
            g_flag[idx]   = (c > 0) ? 1.0f : 0.0f;
            g_cnt[idx]    = 0;   // self-clean for next replay
            run += c;
        }
    }
    if (t == SCAN_T - 1) g_rowoff[N_NODES] = N_EDGES;
}

__global__ __launch_bounds__(256)
void fill_csr_kernel(const void* __restrict__ eidx) {
    const int idx64 = detect_idx64_block(eidx);
    const int e = blockIdx.x * blockDim.x + threadIdx.x;
    if (e >= N_EDGES) return;
    int src, dst;
    if (idx64) {
        const long long* ep = (const long long*)eidx;
        src = (int)ep[e]; dst = (int)ep[N_EDGES + e];
    } else {
        const int* ep = (const int*)eidx;
        src = ep[e]; dst = ep[N_EDGES + e];
    }
    const int pos = atomicAdd(&g_cursor[dst], 1);
    g_eadj[pos] = src;
}

// ---------------------------------------------------------------------------
// Gathers: one warp per node, lane owns one float4, unroll 8 (dual acc)
// ---------------------------------------------------------------------------
__global__ __launch_bounds__(256)
void gather_kernel(const float* __restrict__ src_feat, float* __restrict__ dst_feat) {
    const int node = (blockIdx.x * blockDim.x + threadIdx.x) >> 5;
    if (node >= N_NODES) return;
    const int lane = threadIdx.x & 31;
    const int beg = g_rowoff[node];
    const int end = g_rowoff[node + 1];
    const float4* f4 = (const float4*)src_feat;

    float4 acc0 = make_float4(0.f, 0.f, 0.f, 0.f);
    float4 acc1 = make_float4(0.f, 0.f, 0.f, 0.f);
    int i = beg;
    for (; i + 8 <= end; i += 8) {
        int s[8];
        #pragma unroll
        for (int j = 0; j < 8; ++j) s[j] = g_eadj[i + j];
        float4 v[8];
        #pragma unroll
        for (int j = 0; j < 8; ++j) v[j] = __ldg(&f4[(size_t)s[j] * 32 + lane]);
        #pragma unroll
        for (int j = 0; j < 8; j += 2) {
            acc0.x += v[j].x; acc0.y += v[j].y; acc0.z += v[j].z; acc0.w += v[j].w;
            acc1.x += v[j+1].x; acc1.y += v[j+1].y; acc1.z += v[j+1].z; acc1.w += v[j+1].w;
        }
    }
    for (; i < end; ++i) {
        const int s0 = g_eadj[i];
        float4 v0 = __ldg(&f4[(size_t)s0 * 32 + lane]);
        acc0.x += v0.x; acc0.y += v0.y; acc0.z += v0.z; acc0.w += v0.w;
    }
    const float w = g_invdeg[node];
    float4 o;
    o.x = (acc0.x + acc1.x) * w;
    o.y = (acc0.y + acc1.y) * w;
    o.z = (acc0.z + acc1.z) * w;
    o.w = (acc0.w + acc1.w) * w;
    ((float4*)dst_feat)[(size_t)node * 32 + lane] = o;
}

// ---------------------------------------------------------------------------
// GEMM core (R6 4x2 layout). SEG_BEG/SEG_END select K segments; ACCUM decides
// whether the epilogue writes (with c + flag*d) or accumulates into out.
// ---------------------------------------------------------------------------
template<int SEG_BEG, int SEG_END, bool WRITE>
__device__ __forceinline__
void gemm_body(const float* __restrict__ A0,   // seg 0 source (or nullptr)
               const float* __restrict__ A1,   // seg 1 source (or nullptr)
               const float* __restrict__ A2s,  // seg 2 source (or nullptr)
               float* __restrict__ out, int M) {
    const int tid  = threadIdx.x;
    const int wid  = tid >> 5;
    const int lane = tid & 31;
    const int g    = lane >> 2;
    const int tq   = lane & 3;
    const int m0   = blockIdx.x * 128;
    const int moff = (wid >> 1) * 32;
    const int noff = (wid & 1) * 64;

    int   rows[4];
    bool  rowok[4];
    float flag[4];
    #pragma unroll
    for (int r = 0; r < 4; ++r) {
        const int mi = r >> 1, h = r & 1;
        rows[r]  = m0 + moff + mi * 16 + h * 8 + g;
        rowok[r] = rows[r] < M;
        flag[r]  = rowok[r] ? g_flag[rows[r]] : 0.f;
    }

    float acc[2][8][4];
    #pragma unroll
    for (int mi = 0; mi < 2; ++mi)
        #pragma unroll
        for (int ni = 0; ni < 8; ++ni)
            #pragma unroll
            for (int q = 0; q < 4; ++q) acc[mi][ni][q] = 0.f;

    #pragma unroll 1
    for (int s = SEG_BEG; s < SEG_END; ++s) {
        const float* Asrc = (s == 0) ? A0 : ((s == 1) ? A1 : A2s);

        #pragma unroll 1
        for (int kt = 0; kt < 8; ++kt) {
            const int kk  = kt * 16;
            const int ktg = s * 8 + kt;

            uint4 bf[8];
            #pragma unroll
            for (int ni = 0; ni < 8; ++ni) {
                const int n = noff + ni * 8 + g;
                bf[ni] = g_Upk[(n * 24 + ktg) * 4 + tq];
            }

            uint32_t ah[2][4], al[2][4];
            #pragma unroll
            for (int mi = 0; mi < 2; ++mi)
                #pragma unroll
                for (int h = 0; h < 2; ++h) {
                    const int r = mi * 2 + h;
                    #pragma unroll
                    for (int kh = 0; kh < 2; ++kh) {
                        float2 v = make_float2(0.f, 0.f);
                        if (rowok[r])
                            v = *(const float2*)(Asrc + (size_t)rows[r] * 128
                                                 + kk + tq * 2 + kh * 8);
                        split2(v, ah[mi][kh * 2 + h], al[mi][kh * 2 + h]);
                    }
                }

            #pragma unroll
            for (int mi = 0; mi < 2; ++mi)
                #pragma unroll
                for (int ni = 0; ni < 8; ++ni) {
                    uint32_t bh[2] = {bf[ni].x, bf[ni].y};
                    uint32_t bl[2] = {bf[ni].z, bf[ni].w};
                    mma16816(acc[mi][ni], ah[mi], bh);
                    mma16816(acc[mi][ni], al[mi], bh);
                    mma16816(acc[mi][ni], ah[mi], bl);
                }
        }
    }

    #pragma unroll
    for (int ni = 0; ni < 8; ++ni) {
        const int col = noff + ni * 8 + tq * 2;
        const float2 cc = *(const float2*)(g_c + col);
        const float2 dd = *(const float2*)(g_d + col);
        #pragma unroll
        for (int mi = 0; mi < 2; ++mi)
            #pragma unroll
            for (int h = 0; h < 2; ++h) {
                const int r = mi * 2 + h;
                if (rowok[r]) {
                    float* p = out + (size_t)rows[r] * 128 + col;
                    float2 o;
                    if (WRITE) {
                        o.x = acc[mi][ni][h * 2 + 0] + cc.x + flag[r] * dd.x;
                        o.y = acc[mi][ni][h * 2 + 1] + cc.y + flag[r] * dd.y;
                    } else {
                        float2 prev = *(const float2*)p;
                        o.x = prev.x + acc[mi][ni][h * 2 + 0];
                        o.y = prev.y + acc[mi][ni][h * 2 + 1];
                    }
                    *(float2*)p = o;
                }
            }
    }
}

// gemm_x: out = x @ U3^T + c + flag*d   (segment 2 only)
__global__ __launch_bounds__(256)
void gemm_x_kernel(const float* __restrict__ x, float* __restrict__ out, int M) {
    gemm_body<2, 3, true>(nullptr, nullptr, x, out, M);
}

// gemm_acc: out += A2 @ U1^T + m1 @ U2^T   (segments 0,1)
__global__ __launch_bounds__(256)
void gemm_acc_kernel(float* __restrict__ out, int M) {
    gemm_body<0, 2, false>(g_A2, g_m1, nullptr, out, M);
}

// ---------------------------------------------------------------------------
// Launch (8 work items; capture slot 5 = gemm_x)
// ---------------------------------------------------------------------------
extern "C" void kernel_launch(void* const* d_in, const int* in_sizes, int n_in,
                              void* d_out, int out_size) {
    const float* x    = (const float*)d_in[0];
    const void*  eidx = d_in[1];
    const float* W_l1 = (const float*)d_in[2];
    const float* b_l1 = (const float*)d_in[3];
    const float* W_r1 = (const float*)d_in[4];
    const float* W_l2 = (const float*)d_in[5];
    const float* b_l2 = (const float*)d_in[6];
    const float* W_r2 = (const float*)d_in[7];
    float* out = (float*)d_out;

    float *p_m1, *p_A2;
    cudaGetSymbolAddress((void**)&p_m1, g_m1);
    cudaGetSymbolAddress((void**)&p_A2, g_A2);

    // 1) weights (independent)
    weight_kernel<<<(128 * 96 + 128 + 255) / 256, 256>>>(W_l1, W_r1, W_l2, W_r2, b_l1, b_l2);
    // 2) count
    count_kernel<<<(N_EDGES + 255) / 256, 256>>>(eidx);
    // 3) scan (self-cleans g_cnt)
    scan_kernel<<<1, SCAN_T>>>();
    // 4) CSR fill
    fill_csr_kernel<<<(N_EDGES + 255) / 256, 256>>>(eidx);
    // 5) gemm_x (profiled slot)
    gemm_x_kernel<<<(N_NODES + 127) / 128, 256>>>(x, out, N_NODES);
    // 6-7) gathers
    const unsigned gblocks = (N_NODES * 32 + 255) / 256;
    gather_kernel<<<gblocks, 256>>>(x, p_m1);
    gather_kernel<<<gblocks, 256>>>(p_m1, p_A2);
    // 8) gemm accumulate
    gemm_acc_kernel<<<(N_NODES + 127) / 128, 256>>>(out, N_NODES);
}

// round 9
// speedup vs baseline: 1.0900x; 1.0900x over previous
#include <cuda_runtime.h>
#include <cuda_fp16.h>
#include <cstdint>
#include <cstddef>

// Problem constants (match reference)
#define N_NODES 50000
#define N_EDGES 800000
#define D_IN    128
#define D_HID   256
#define D_OUT   128

// ---------------------------------------------------------------------------
// Pipeline (7 launches, R6 structure; g_cnt self-cleaning):
//   count   : dst histogram (inline idx-dtype detect)
//   scan    : rowoff/cursor/invdeg/flag; zeroes g_cnt for next replay
//   fill    : CSR adjacency
//   gather1 : m1[n] = invdeg[n] * sum x[s]
//   gather2 : A2[n] = invdeg[n] * sum m1[s]
//   weight  : U fragment-packed fp16 + c, d
//   gemm    : out = A2@U1^T + m1@U2^T + x@U3^T + c + flag*d
//             (mma.sync fp16: A hi/lo 2-term, B single fp16)
// ---------------------------------------------------------------------------

// Device scratch
__device__ int   g_cnt[N_NODES];          // zero at load; scan re-zeroes per replay
__device__ int   g_rowoff[N_NODES + 1];
__device__ int   g_cursor[N_NODES];
__device__ int   g_eadj[N_EDGES];
__device__ float g_invdeg[N_NODES];
__device__ float g_flag[N_NODES];
__device__ float g_m1[(size_t)N_NODES * 128];
__device__ float g_A2[(size_t)N_NODES * 128];
__device__ uint2 g_Upk[128 * 24 * 4];     // fp16 fragment-packed U
__device__ float g_c[128];
__device__ float g_d[128];

// ---------------------------------------------------------------------------
// mma helpers (fp16 inputs, fp32 accumulate)
// ---------------------------------------------------------------------------
__device__ __forceinline__ void mma16816h(float* d, const uint32_t* a, const uint32_t* b) {
    asm volatile(
        "mma.sync.aligned.m16n8k16.row.col.f32.f16.f16.f32 "
        "{%0,%1,%2,%3}, {%4,%5,%6,%7}, {%8,%9}, {%0,%1,%2,%3};"
        : "+f"(d[0]), "+f"(d[1]), "+f"(d[2]), "+f"(d[3])
        : "r"(a[0]), "r"(a[1]), "r"(a[2]), "r"(a[3]), "r"(b[0]), "r"(b[1]));
}
// split float2 -> packed fp16x2 hi and lo (2-term: v ~= hi + lo, err ~2^-22)
__device__ __forceinline__ void split2h(float2 v, uint32_t& hi, uint32_t& lo) {
    __half2 h = __float22half2_rn(v);
    float2 hv = __half22float2(h);
    __half2 l = __float22half2_rn(make_float2(v.x - hv.x, v.y - hv.y));
    hi = *reinterpret_cast<uint32_t*>(&h);
    lo = *reinterpret_cast<uint32_t*>(&l);
}
__device__ __forceinline__ uint32_t packh2(float a, float b) {
    __half2 h = __float22half2_rn(make_float2(a, b));
    return *reinterpret_cast<uint32_t*>(&h);
}

// Per-block idx-dtype detection (int32 read as int64 -> >= 2^32 a.s.)
__device__ __forceinline__ int detect_idx64_block(const void* eidx) {
    __shared__ int s_idx64;
    if (threadIdx.x < 32) {
        const long long* p = (const long long*)eidx;
        int ok = 1;
        #pragma unroll
        for (int i = 0; i < 16; ++i) {
            long long v = p[threadIdx.x * 16 + i];
            ok &= (v >= 0 && v < (long long)N_NODES);
        }
        unsigned m = __ballot_sync(0xffffffffu, ok);
        if (threadIdx.x == 0) s_idx64 = (m == 0xffffffffu) ? 1 : 0;
    }
    __syncthreads();
    return s_idx64;
}

// ---------------------------------------------------------------------------
// CSR build
// ---------------------------------------------------------------------------
__global__ __launch_bounds__(256)
void count_kernel(const void* __restrict__ eidx) {
    const int idx64 = detect_idx64_block(eidx);
    const int e = blockIdx.x * blockDim.x + threadIdx.x;
    if (e >= N_EDGES) return;
    int dst;
    if (idx64) dst = (int)((const long long*)eidx)[N_EDGES + e];
    else       dst = ((const int*)eidx)[N_EDGES + e];
    atomicAdd(&g_cnt[dst], 1);
}

#define SCAN_T 1024
#define SCAN_CH 49
__global__ __launch_bounds__(SCAN_T)
void scan_kernel() {
    __shared__ int wsum[32];
    const int t = threadIdx.x;
    const int base = t * SCAN_CH;

    int cnt[SCAN_CH];
    int lsum = 0;
    #pragma unroll 7
    for (int i = 0; i < SCAN_CH; ++i) {
        const int idx = base + i;
        cnt[i] = (idx < N_NODES) ? g_cnt[idx] : 0;
        lsum += cnt[i];
    }

    int v = lsum;
    #pragma unroll
    for (int d = 1; d < 32; d <<= 1) {
        int n = __shfl_up_sync(0xffffffffu, v, d);
        if ((t & 31) >= d) v += n;
    }
    if ((t & 31) == 31) wsum[t >> 5] = v;
    __syncthreads();
    if (t < 32) {
        int w = wsum[t];
        #pragma unroll
        for (int d = 1; d < 32; d <<= 1) {
            int n = __shfl_up_sync(0xffffffffu, w, d);
            if (t >= d) w += n;
        }
        wsum[t] = w;
    }
    __syncthreads();
    int run = v + ((t >= 32) ? wsum[(t >> 5) - 1] : 0) - lsum;

    #pragma unroll 7
    for (int i = 0; i < SCAN_CH; ++i) {
        const int idx = base + i;
        if (idx < N_NODES) {
            const int c = cnt[i];
            g_rowoff[idx] = run;
            g_cursor[idx] = run;
            g_invdeg[idx] = 1.0f / fmaxf((float)c, 1.0f);
            g_flag[idx]   = (c > 0) ? 1.0f : 0.0f;
            g_cnt[idx]    = 0;   // self-clean for next replay
            run += c;
        }
    }
    if (t == SCAN_T - 1) g_rowoff[N_NODES] = N_EDGES;
}

__global__ __launch_bounds__(256)
void fill_csr_kernel(const void* __restrict__ eidx) {
    const int idx64 = detect_idx64_block(eidx);
    const int e = blockIdx.x * blockDim.x + threadIdx.x;
    if (e >= N_EDGES) return;
    int src, dst;
    if (idx64) {
        const long long* ep = (const long long*)eidx;
        src = (int)ep[e]; dst = (int)ep[N_EDGES + e];
    } else {
        const int* ep = (const int*)eidx;
        src = ep[e]; dst = ep[N_EDGES + e];
    }
    const int pos = atomicAdd(&g_cursor[dst], 1);
    g_eadj[pos] = src;
}

// ---------------------------------------------------------------------------
// Gathers: one warp per node, lane owns one float4, unroll 4 (R6 config)
// ---------------------------------------------------------------------------
__global__ __launch_bounds__(256)
void gather_kernel(const float* __restrict__ src_feat, float* __restrict__ dst_feat) {
    const int node = (blockIdx.x * blockDim.x + threadIdx.x) >> 5;
    if (node >= N_NODES) return;
    const int lane = threadIdx.x & 31;
    const int beg = g_rowoff[node];
    const int end = g_rowoff[node + 1];
    const float4* f4 = (const float4*)src_feat;

    float4 acc = make_float4(0.f, 0.f, 0.f, 0.f);
    int i = beg;
    for (; i + 4 <= end; i += 4) {
        const int s0 = g_eadj[i];
        const int s1 = g_eadj[i + 1];
        const int s2 = g_eadj[i + 2];
        const int s3 = g_eadj[i + 3];
        float4 v0 = __ldg(&f4[(size_t)s0 * 32 + lane]);
        float4 v1 = __ldg(&f4[(size_t)s1 * 32 + lane]);
        float4 v2 = __ldg(&f4[(size_t)s2 * 32 + lane]);
        float4 v3 = __ldg(&f4[(size_t)s3 * 32 + lane]);
        acc.x += (v0.x + v1.x) + (v2.x + v3.x);
        acc.y += (v0.y + v1.y) + (v2.y + v3.y);
        acc.z += (v0.z + v1.z) + (v2.z + v3.z);
        acc.w += (v0.w + v1.w) + (v2.w + v3.w);
    }
    for (; i < end; ++i) {
        const int s0 = g_eadj[i];
        float4 v0 = __ldg(&f4[(size_t)s0 * 32 + lane]);
        acc.x += v0.x; acc.y += v0.y; acc.z += v0.z; acc.w += v0.w;
    }
    const float w = g_invdeg[node];
    acc.x *= w; acc.y *= w; acc.z *= w; acc.w *= w;
    ((float4*)dst_feat)[(size_t)node * 32 + lane] = acc;
}

// ---------------------------------------------------------------------------
// Weights: U fragment-packed fp16 + c, d.
// Upk[((n*24)+ktg)*4+tq] = {h(k0,k0+1), h(k0+8,k0+9)},
// k0 = (ktg%8)*16 + 2*tq, seg = ktg/8 -> U1/U2/U3.
// ---------------------------------------------------------------------------
__global__ __launch_bounds__(256)
void weight_kernel(const float* __restrict__ Wl1,
                   const float* __restrict__ Wr1,
                   const float* __restrict__ Wl2,
                   const float* __restrict__ Wr2,
                   const float* __restrict__ b1,
                   const float* __restrict__ b2) {
    const int tid = blockIdx.x * blockDim.x + threadIdx.x;

    if (tid < 128 * 96) {
        const int n   = tid / 96;
        const int rem = tid - n * 96;
        const int ktg = rem >> 2;
        const int tq  = rem & 3;
        const int seg = ktg >> 3;
        const int k0  = (ktg & 7) * 16 + 2 * tq;

        float u[4] = {0.f, 0.f, 0.f, 0.f};   // k0, k0+1, k0+8, k0+9
        const float* A1 = Wl2 + (size_t)n * 256;
        const float* A2 = Wr2 + (size_t)n * 256;
        #pragma unroll 4
        for (int t = 0; t < 256; ++t) {
            const float wl2 = A1[t];
            const float wr2 = A2[t];
            const float* rl = Wl1 + (size_t)t * 128 + k0;
            const float* rr = Wr1 + (size_t)t * 128 + k0;
            if (seg == 0) {
                u[0] += wl2 * rl[0]; u[1] += wl2 * rl[1];
                u[2] += wl2 * rl[8]; u[3] += wl2 * rl[9];
            } else if (seg == 1) {
                u[0] += wl2 * rr[0] + wr2 * rl[0];
                u[1] += wl2 * rr[1] + wr2 * rl[1];
                u[2] += wl2 * rr[8] + wr2 * rl[8];
                u[3] += wl2 * rr[9] + wr2 * rl[9];
            } else {
                u[0] += wr2 * rr[0]; u[1] += wr2 * rr[1];
                u[2] += wr2 * rr[8]; u[3] += wr2 * rr[9];
            }
        }
        g_Upk[tid] = make_uint2(packh2(u[0], u[1]), packh2(u[2], u[3]));
    } else if (tid < 128 * 96 + 128) {
        const int a = tid - 128 * 96;
        float c = 0.f, d = 0.f;
        #pragma unroll 4
        for (int k = 0; k < 256; ++k) {
            c += Wr2[a * 256 + k] * b1[k];
            d += Wl2[a * 256 + k] * b1[k];
        }
        g_c[a] = b2[a] + c;
        g_d[a] = d;
    }
}

// ---------------------------------------------------------------------------
// Tensor-core GEMM: out[M,128] = [A2 | m1 | x] @ U^T + c + flag*d
// R6 4x2 warp layout; fp16 A 2-term split, B single fp16 (2 MMAs per k16).
// ---------------------------------------------------------------------------
__global__ __launch_bounds__(256)
void mma_gemm_kernel(const float* __restrict__ x, float* __restrict__ out, int M) {
    const int tid  = threadIdx.x;
    const int wid  = tid >> 5;
    const int lane = tid & 31;
    const int g    = lane >> 2;
    const int tq   = lane & 3;
    const int m0   = blockIdx.x * 128;
    const int moff = (wid >> 1) * 32;
    const int noff = (wid & 1) * 64;

    int   rows[4];
    bool  rowok[4];
    float flag[4];
    #pragma unroll
    for (int r = 0; r < 4; ++r) {
        const int mi = r >> 1, h = r & 1;
        rows[r]  = m0 + moff + mi * 16 + h * 8 + g;
        rowok[r] = rows[r] < M;
        flag[r]  = rowok[r] ? g_flag[rows[r]] : 0.f;
    }

    float acc[2][8][4];
    #pragma unroll
    for (int mi = 0; mi < 2; ++mi)
        #pragma unroll
        for (int ni = 0; ni < 8; ++ni)
            #pragma unroll
            for (int q = 0; q < 4; ++q) acc[mi][ni][q] = 0.f;

    #pragma unroll 1
    for (int s = 0; s < 3; ++s) {
        const float* Asrc = (s == 0) ? g_A2 : ((s == 1) ? g_m1 : x);

        #pragma unroll 1
        for (int kt = 0; kt < 8; ++kt) {
            const int kk  = kt * 16;
            const int ktg = s * 8 + kt;

            // B fragments (single fp16): one uint2 per ni
            uint2 bf[8];
            #pragma unroll
            for (int ni = 0; ni < 8; ++ni) {
                const int n = noff + ni * 8 + g;
                bf[ni] = g_Upk[(n * 24 + ktg) * 4 + tq];
            }

            // A fragments (load fp32, split fp16 hi/lo)
            uint32_t ah[2][4], al[2][4];
            #pragma unroll
            for (int mi = 0; mi < 2; ++mi)
                #pragma unroll
                for (int h = 0; h < 2; ++h) {
                    const int r = mi * 2 + h;
                    #pragma unroll
                    for (int kh = 0; kh < 2; ++kh) {
                        float2 v = make_float2(0.f, 0.f);
                        if (rowok[r])
                            v = *(const float2*)(Asrc + (size_t)rows[r] * 128
                                                 + kk + tq * 2 + kh * 8);
                        split2h(v, ah[mi][kh * 2 + h], al[mi][kh * 2 + h]);
                    }
                }

            // MMAs: 2 per (mi, ni)
            #pragma unroll
            for (int mi = 0; mi < 2; ++mi)
                #pragma unroll
                for (int ni = 0; ni < 8; ++ni) {
                    uint32_t b2r[2] = {bf[ni].x, bf[ni].y};
                    mma16816h(acc[mi][ni], ah[mi], b2r);
                    mma16816h(acc[mi][ni], al[mi], b2r);
                }
        }
    }

    #pragma unroll
    for (int ni = 0; ni < 8; ++ni) {
        const int col = noff + ni * 8 + tq * 2;
        const float2 cc = *(const float2*)(g_c + col);
        const float2 dd = *(const float2*)(g_d + col);
        #pragma unroll
        for (int mi = 0; mi < 2; ++mi)
            #pragma unroll
            for (int h = 0; h < 2; ++h) {
                const int r = mi * 2 + h;
                if (rowok[r]) {
                    float2 o;
                    o.x = acc[mi][ni][h * 2 + 0] + cc.x + flag[r] * dd.x;
                    o.y = acc[mi][ni][h * 2 + 1] + cc.y + flag[r] * dd.y;
                    *(float2*)(out + (size_t)rows[r] * 128 + col) = o;
                }
            }
    }
}

// ---------------------------------------------------------------------------
// Launch (7 kernels, R6 order minus memset)
// ---------------------------------------------------------------------------
extern "C" void kernel_launch(void* const* d_in, const int* in_sizes, int n_in,
                              void* d_out, int out_size) {
    const float* x    = (const float*)d_in[0];
    const void*  eidx = d_in[1];
    const float* W_l1 = (const float*)d_in[2];
    const float* b_l1 = (const float*)d_in[3];
    const float* W_r1 = (const float*)d_in[4];
    const float* W_l2 = (const float*)d_in[5];
    const float* b_l2 = (const float*)d_in[6];
    const float* W_r2 = (const float*)d_in[7];
    float* out = (float*)d_out;

    float *p_m1, *p_A2;
    cudaGetSymbolAddress((void**)&p_m1, g_m1);
    cudaGetSymbolAddress((void**)&p_A2, g_A2);

    // 1) count
    count_kernel<<<(N_EDGES + 255) / 256, 256>>>(eidx);
    // 2) scan (self-cleans g_cnt)
    scan_kernel<<<1, SCAN_T>>>();
    // 3) CSR fill
    fill_csr_kernel<<<(N_EDGES + 255) / 256, 256>>>(eidx);
    // 4-5) gathers
    const unsigned gblocks = (N_NODES * 32 + 255) / 256;
    gather_kernel<<<gblocks, 256>>>(x, p_m1);
    gather_kernel<<<gblocks, 256>>>(p_m1, p_A2);
    // 6) weights (fp16 packed)
    weight_kernel<<<(128 * 96 + 128 + 255) / 256, 256>>>(W_l1, W_r1, W_l2, W_r2, b_l1, b_l2);
    // 7) fused tensor-core GEMM
    mma_gemm_kernel<<<(N_NODES + 127) / 128, 256>>>(x, out, N_NODES);
}

// round 10
// speedup vs baseline: 1.4767x; 1.3547x over previous
#include <cuda_runtime.h>
#include <cuda_fp16.h>
#include <cstdint>
#include <cstddef>

// Problem constants (match reference)
#define N_NODES 50000
#define N_EDGES 800000
#define D_IN    128
#define D_HID   256
#define D_OUT   128

// ---------------------------------------------------------------------------
// Pipeline (6 launches):
//   count   : dst histogram (inline idx-dtype detect)
//   scanW   : block 0 = scan (rowoff/cursor/invdeg/flag, self-clean g_cnt);
//             blocks 1-13 = weight pre-products (coalesced-for-GEMM layout)
//   fill    : CSR adjacency
//   gather1 : m1[n] = invdeg[n] * sum x[s]
//   gather2 : A2[n] = invdeg[n] * sum m1[s]
//   gemm    : out = A2@U1^T + m1@U2^T + x@U3^T + c + flag*d
//             (mma.sync fp16: A hi/lo 2-term, B single fp16, coalesced B frags)
// ---------------------------------------------------------------------------

// Device scratch
__device__ int   g_cnt[N_NODES];          // zero at load; scanW re-zeroes per replay
__device__ int   g_rowoff[N_NODES + 1];
__device__ int   g_cursor[N_NODES];
__device__ int   g_eadj[N_EDGES];
__device__ float g_invdeg[N_NODES];
__device__ float g_flag[N_NODES];
__device__ float g_m1[(size_t)N_NODES * 128];
__device__ float g_A2[(size_t)N_NODES * 128];
// B fragments, warp-coalesced: index = (ktg*128 + n)*4 + tq
__device__ uint2 g_Upk[24 * 128 * 4];
__device__ float g_c[128];
__device__ float g_d[128];

// ---------------------------------------------------------------------------
// mma helpers (fp16 inputs, fp32 accumulate)
// ---------------------------------------------------------------------------
__device__ __forceinline__ void mma16816h(float* d, const uint32_t* a, const uint32_t* b) {
    asm volatile(
        "mma.sync.aligned.m16n8k16.row.col.f32.f16.f16.f32 "
        "{%0,%1,%2,%3}, {%4,%5,%6,%7}, {%8,%9}, {%0,%1,%2,%3};"
        : "+f"(d[0]), "+f"(d[1]), "+f"(d[2]), "+f"(d[3])
        : "r"(a[0]), "r"(a[1]), "r"(a[2]), "r"(a[3]), "r"(b[0]), "r"(b[1]));
}
__device__ __forceinline__ void split2h(float2 v, uint32_t& hi, uint32_t& lo) {
    __half2 h = __float22half2_rn(v);
    float2 hv = __half22float2(h);
    __half2 l = __float22half2_rn(make_float2(v.x - hv.x, v.y - hv.y));
    hi = *reinterpret_cast<uint32_t*>(&h);
    lo = *reinterpret_cast<uint32_t*>(&l);
}
__device__ __forceinline__ uint32_t packh2(float a, float b) {
    __half2 h = __float22half2_rn(make_float2(a, b));
    return *reinterpret_cast<uint32_t*>(&h);
}

// Per-block idx-dtype detection (int32 read as int64 -> >= 2^32 a.s.)
__device__ __forceinline__ int detect_idx64_block(const void* eidx) {
    __shared__ int s_idx64;
    if (threadIdx.x < 32) {
        const long long* p = (const long long*)eidx;
        int ok = 1;
        #pragma unroll
        for (int i = 0; i < 16; ++i) {
            long long v = p[threadIdx.x * 16 + i];
            ok &= (v >= 0 && v < (long long)N_NODES);
        }
        unsigned m = __ballot_sync(0xffffffffu, ok);
        if (threadIdx.x == 0) s_idx64 = (m == 0xffffffffu) ? 1 : 0;
    }
    __syncthreads();
    return s_idx64;
}

// ---------------------------------------------------------------------------
// CSR build
// ---------------------------------------------------------------------------
__global__ __launch_bounds__(256)
void count_kernel(const void* __restrict__ eidx) {
    const int idx64 = detect_idx64_block(eidx);
    const int e = blockIdx.x * blockDim.x + threadIdx.x;
    if (e >= N_EDGES) return;
    int dst;
    if (idx64) dst = (int)((const long long*)eidx)[N_EDGES + e];
    else       dst = ((const int*)eidx)[N_EDGES + e];
    atomicAdd(&g_cnt[dst], 1);
}

// ---------------------------------------------------------------------------
// scanW: block 0 scans; blocks 1..13 compute weight pre-products.
// Weight item layout matches GEMM fragment fetch:
//   g_Upk[(ktg*128 + n)*4 + tq] = {h(k0,k0+1), h(k0+8,k0+9)},
//   k0 = (ktg%8)*16 + 2*tq, seg = ktg/8 -> U1/U2/U3.
// ---------------------------------------------------------------------------
#define SCAN_T 1024
#define SCAN_CH 49
#define WEIGHT_ITEMS (128 * 96 + 128)   // 12416

__global__ __launch_bounds__(SCAN_T)
void scanW_kernel(const float* __restrict__ Wl1,
                  const float* __restrict__ Wr1,
                  const float* __restrict__ Wl2,
                  const float* __restrict__ Wr2,
                  const float* __restrict__ b1,
                  const float* __restrict__ b2) {
    if (blockIdx.x == 0) {
        __shared__ int wsum[32];
        const int t = threadIdx.x;
        const int base = t * SCAN_CH;

        int cnt[SCAN_CH];
        int lsum = 0;
        #pragma unroll 7
        for (int i = 0; i < SCAN_CH; ++i) {
            const int idx = base + i;
            cnt[i] = (idx < N_NODES) ? g_cnt[idx] : 0;
            lsum += cnt[i];
        }

        int v = lsum;
        #pragma unroll
        for (int d = 1; d < 32; d <<= 1) {
            int n = __shfl_up_sync(0xffffffffu, v, d);
            if ((t & 31) >= d) v += n;
        }
        if ((t & 31) == 31) wsum[t >> 5] = v;
        __syncthreads();
        if (t < 32) {
            int w = wsum[t];
            #pragma unroll
            for (int d = 1; d < 32; d <<= 1) {
                int n = __shfl_up_sync(0xffffffffu, w, d);
                if (t >= d) w += n;
            }
            wsum[t] = w;
        }
        __syncthreads();
        int run = v + ((t >= 32) ? wsum[(t >> 5) - 1] : 0) - lsum;

        #pragma unroll 7
        for (int i = 0; i < SCAN_CH; ++i) {
            const int idx = base + i;
            if (idx < N_NODES) {
                const int c = cnt[i];
                g_rowoff[idx] = run;
                g_cursor[idx] = run;
                g_invdeg[idx] = 1.0f / fmaxf((float)c, 1.0f);
                g_flag[idx]   = (c > 0) ? 1.0f : 0.0f;
                g_cnt[idx]    = 0;   // self-clean for next replay
                run += c;
            }
        }
        if (t == SCAN_T - 1) g_rowoff[N_NODES] = N_EDGES;
        return;
    }

    // ---- weight blocks ----
    const int tid = (blockIdx.x - 1) * SCAN_T + threadIdx.x;
    if (tid < 128 * 96) {
        const int n   = tid / 96;
        const int rem = tid - n * 96;
        const int ktg = rem >> 2;
        const int tq  = rem & 3;
        const int seg = ktg >> 3;
        const int k0  = (ktg & 7) * 16 + 2 * tq;

        float u[4] = {0.f, 0.f, 0.f, 0.f};   // k0, k0+1, k0+8, k0+9
        const float* A1 = Wl2 + (size_t)n * 256;
        const float* A2 = Wr2 + (size_t)n * 256;
        #pragma unroll 4
        for (int t = 0; t < 256; ++t) {
            const float wl2 = A1[t];
            const float wr2 = A2[t];
            const float* rl = Wl1 + (size_t)t * 128 + k0;
            const float* rr = Wr1 + (size_t)t * 128 + k0;
            if (seg == 0) {
                u[0] += wl2 * rl[0]; u[1] += wl2 * rl[1];
                u[2] += wl2 * rl[8]; u[3] += wl2 * rl[9];
            } else if (seg == 1) {
                u[0] += wl2 * rr[0] + wr2 * rl[0];
                u[1] += wl2 * rr[1] + wr2 * rl[1];
                u[2] += wl2 * rr[8] + wr2 * rl[8];
                u[3] += wl2 * rr[9] + wr2 * rl[9];
            } else {
                u[0] += wr2 * rr[0]; u[1] += wr2 * rr[1];
                u[2] += wr2 * rr[8]; u[3] += wr2 * rr[9];
            }
        }
        g_Upk[(ktg * 128 + n) * 4 + tq] =
            make_uint2(packh2(u[0], u[1]), packh2(u[2], u[3]));
    } else if (tid < WEIGHT_ITEMS) {
        const int a = tid - 128 * 96;
        float c = 0.f, d = 0.f;
        #pragma unroll 4
        for (int k = 0; k < 256; ++k) {
            c += Wr2[a * 256 + k] * b1[k];
            d += Wl2[a * 256 + k] * b1[k];
        }
        g_c[a] = b2[a] + c;
        g_d[a] = d;
    }
}

__global__ __launch_bounds__(256)
void fill_csr_kernel(const void* __restrict__ eidx) {
    const int idx64 = detect_idx64_block(eidx);
    const int e = blockIdx.x * blockDim.x + threadIdx.x;
    if (e >= N_EDGES) return;
    int src, dst;
    if (idx64) {
        const long long* ep = (const long long*)eidx;
        src = (int)ep[e]; dst = (int)ep[N_EDGES + e];
    } else {
        const int* ep = (const int*)eidx;
        src = ep[e]; dst = ep[N_EDGES + e];
    }
    const int pos = atomicAdd(&g_cursor[dst], 1);
    g_eadj[pos] = src;
}

// ---------------------------------------------------------------------------
// Gathers: one warp per node, lane owns one float4, unroll 4
// ---------------------------------------------------------------------------
__global__ __launch_bounds__(256)
void gather_kernel(const float* __restrict__ src_feat, float* __restrict__ dst_feat) {
    const int node = (blockIdx.x * blockDim.x + threadIdx.x) >> 5;
    if (node >= N_NODES) return;
    const int lane = threadIdx.x & 31;
    const int beg = g_rowoff[node];
    const int end = g_rowoff[node + 1];
    const float4* f4 = (const float4*)src_feat;

    float4 acc = make_float4(0.f, 0.f, 0.f, 0.f);
    int i = beg;
    for (; i + 4 <= end; i += 4) {
        const int s0 = g_eadj[i];
        const int s1 = g_eadj[i + 1];
        const int s2 = g_eadj[i + 2];
        const int s3 = g_eadj[i + 3];
        float4 v0 = __ldg(&f4[(size_t)s0 * 32 + lane]);
        float4 v1 = __ldg(&f4[(size_t)s1 * 32 + lane]);
        float4 v2 = __ldg(&f4[(size_t)s2 * 32 + lane]);
        float4 v3 = __ldg(&f4[(size_t)s3 * 32 + lane]);
        acc.x += (v0.x + v1.x) + (v2.x + v3.x);
        acc.y += (v0.y + v1.y) + (v2.y + v3.y);
        acc.z += (v0.z + v1.z) + (v2.z + v3.z);
        acc.w += (v0.w + v1.w) + (v2.w + v3.w);
    }
    for (; i < end; ++i) {
        const int s0 = g_eadj[i];
        float4 v0 = __ldg(&f4[(size_t)s0 * 32 + lane]);
        acc.x += v0.x; acc.y += v0.y; acc.z += v0.z; acc.w += v0.w;
    }
    const float w = g_invdeg[node];
    acc.x *= w; acc.y *= w; acc.z *= w; acc.w *= w;
    ((float4*)dst_feat)[(size_t)node * 32 + lane] = acc;
}

// ---------------------------------------------------------------------------
// Tensor-core GEMM: out[M,128] = [A2 | m1 | x] @ U^T + c + flag*d
// 4x2 warp layout; fp16 A 2-term split, single-fp16 B; B frags fully
// warp-coalesced (lane-linear uint2).
// ---------------------------------------------------------------------------
__global__ __launch_bounds__(256)
void mma_gemm_kernel(const float* __restrict__ x, float* __restrict__ out, int M) {
    const int tid  = threadIdx.x;
    const int wid  = tid >> 5;
    const int lane = tid & 31;
    const int g    = lane >> 2;
    const int tq   = lane & 3;
    const int m0   = blockIdx.x * 128;
    const int moff = (wid >> 1) * 32;
    const int noff = (wid & 1) * 64;

    int   rows[4];
    bool  rowok[4];
    float flag[4];
    #pragma unroll
    for (int r = 0; r < 4; ++r) {
        const int mi = r >> 1, h = r & 1;
        rows[r]  = m0 + moff + mi * 16 + h * 8 + g;
        rowok[r] = rows[r] < M;
        flag[r]  = rowok[r] ? g_flag[rows[r]] : 0.f;
    }

    float acc[2][8][4];
    #pragma unroll
    for (int mi = 0; mi < 2; ++mi)
        #pragma unroll
        for (int ni = 0; ni < 8; ++ni)
            #pragma unroll
            for (int q = 0; q < 4; ++q) acc[mi][ni][q] = 0.f;

    #pragma unroll 1
    for (int s = 0; s < 3; ++s) {
        const float* Asrc = (s == 0) ? g_A2 : ((s == 1) ? g_m1 : x);

        #pragma unroll 1
        for (int kt = 0; kt < 8; ++kt) {
            const int kk  = kt * 16;
            const int ktg = s * 8 + kt;

            // B fragments: lane-linear coalesced loads
            uint2 bf[8];
            #pragma unroll
            for (int ni = 0; ni < 8; ++ni) {
                const int n = noff + ni * 8 + g;
                bf[ni] = g_Upk[(ktg * 128 + n) * 4 + tq];
            }

            // A fragments (load fp32, split fp16 hi/lo)
            uint32_t ah[2][4], al[2][4];
            #pragma unroll
            for (int mi = 0; mi < 2; ++mi)
                #pragma unroll
                for (int h = 0; h < 2; ++h) {
                    const int r = mi * 2 + h;
                    #pragma unroll
                    for (int kh = 0; kh < 2; ++kh) {
                        float2 v = make_float2(0.f, 0.f);
                        if (rowok[r])
                            v = *(const float2*)(Asrc + (size_t)rows[r] * 128
                                                 + kk + tq * 2 + kh * 8);
                        split2h(v, ah[mi][kh * 2 + h], al[mi][kh * 2 + h]);
                    }
                }

            // MMAs: 2 per (mi, ni)
            #pragma unroll
            for (int mi = 0; mi < 2; ++mi)
                #pragma unroll
                for (int ni = 0; ni < 8; ++ni) {
                    uint32_t b2r[2] = {bf[ni].x, bf[ni].y};
                    mma16816h(acc[mi][ni], ah[mi], b2r);
                    mma16816h(acc[mi][ni], al[mi], b2r);
                }
        }
    }

    #pragma unroll
    for (int ni = 0; ni < 8; ++ni) {
        const int col = noff + ni * 8 + tq * 2;
        const float2 cc = *(const float2*)(g_c + col);
        const float2 dd = *(const float2*)(g_d + col);
        #pragma unroll
        for (int mi = 0; mi < 2; ++mi)
            #pragma unroll
            for (int h = 0; h < 2; ++h) {
                const int r = mi * 2 + h;
                if (rowok[r]) {
                    float2 o;
                    o.x = acc[mi][ni][h * 2 + 0] + cc.x + flag[r] * dd.x;
                    o.y = acc[mi][ni][h * 2 + 1] + cc.y + flag[r] * dd.y;
                    *(float2*)(out + (size_t)rows[r] * 128 + col) = o;
                }
            }
    }
}

// ---------------------------------------------------------------------------
// Launch (6 kernels)
// ---------------------------------------------------------------------------
extern "C" void kernel_launch(void* const* d_in, const int* in_sizes, int n_in,
                              void* d_out, int out_size) {
    const float* x    = (const float*)d_in[0];
    const void*  eidx = d_in[1];
    const float* W_l1 = (const float*)d_in[2];
    const float* b_l1 = (const float*)d_in[3];
    const float* W_r1 = (const float*)d_in[4];
    const float* W_l2 = (const float*)d_in[5];
    const float* b_l2 = (const float*)d_in[6];
    const float* W_r2 = (const float*)d_in[7];
    float* out = (float*)d_out;

    float *p_m1, *p_A2;
    cudaGetSymbolAddress((void**)&p_m1, g_m1);
    cudaGetSymbolAddress((void**)&p_A2, g_A2);

    // 1) count
    count_kernel<<<(N_EDGES + 255) / 256, 256>>>(eidx);
    // 2) scan + weights (block 0 scans; 13 weight blocks)
    scanW_kernel<<<1 + (WEIGHT_ITEMS + SCAN_T - 1) / SCAN_T, SCAN_T>>>(
        W_l1, W_r1, W_l2, W_r2, b_l1, b_l2);
    // 3) CSR fill
    fill_csr_kernel<<<(N_EDGES + 255) / 256, 256>>>(eidx);
    // 4-5) gathers
    const unsigned gblocks = (N_NODES * 32 + 255) / 256;
    gather_kernel<<<gblocks, 256>>>(x, p_m1);
    gather_kernel<<<gblocks, 256>>>(p_m1, p_A2);
    // 6) fused tensor-core GEMM
    mma_gemm_kernel<<<(N_NODES + 127) / 128, 256>>>(x, out, N_NODES);
}

// round 11
// speedup vs baseline: 1.6036x; 1.0860x over previous
#include <cuda_runtime.h>
#include <cuda_fp16.h>
#include <cstdint>
#include <cstddef>

// Problem constants (match reference)
#define N_NODES 50000
#define N_EDGES 800000
#define D_IN    128
#define D_HID   256
#define D_OUT   128

// ---------------------------------------------------------------------------
// Pipeline (6 launches):
//   count   : dst histogram (inline idx-dtype detect)
//   scanW   : block 0 = scan (rowoff/cursor/invdeg/flag, self-clean g_cnt);
//             blocks 1-13 = weight pre-products (coalesced-for-GEMM layout)
//   fill    : CSR adjacency
//   gather1 : m1[n] = invdeg[n] * sum x[s]
//   gather2 : A2[n] = invdeg[n] * sum m1[s]
//   gemm    : out = A2@U1^T + m1@U2^T + x@U3^T + c + flag*d
//             (mma.sync fp16 A hi/lo 2-term; A staged via smem — coalesced
//              global loads + LDS fragment fetch; B frags coalesced global)
// ---------------------------------------------------------------------------

// Device scratch
__device__ int   g_cnt[N_NODES];          // zero at load; scanW re-zeroes per replay
__device__ int   g_rowoff[N_NODES + 1];
__device__ int   g_cursor[N_NODES];
__device__ int   g_eadj[N_EDGES];
__device__ float g_invdeg[N_NODES];
__device__ float g_flag[N_NODES];
__device__ float g_m1[(size_t)N_NODES * 128];
__device__ float g_A2[(size_t)N_NODES * 128];
// B fragments, warp-coalesced: index = (ktg*128 + n)*4 + tq
__device__ uint2 g_Upk[24 * 128 * 4];
__device__ float g_c[128];
__device__ float g_d[128];

// smem tile geometry (half): 128 rows x 128 cols, padded stride 132
#define SA_STRIDE 132
#define SA_HALFS  (128 * SA_STRIDE)
#define SMEM_BYTES (2 * SA_HALFS * 2)    // hi + lo tiles, 2B each = 67584

// ---------------------------------------------------------------------------
// mma helpers (fp16 inputs, fp32 accumulate)
// ---------------------------------------------------------------------------
__device__ __forceinline__ void mma16816h(float* d, const uint32_t* a, const uint32_t* b) {
    asm volatile(
        "mma.sync.aligned.m16n8k16.row.col.f32.f16.f16.f32 "
        "{%0,%1,%2,%3}, {%4,%5,%6,%7}, {%8,%9}, {%0,%1,%2,%3};"
        : "+f"(d[0]), "+f"(d[1]), "+f"(d[2]), "+f"(d[3])
        : "r"(a[0]), "r"(a[1]), "r"(a[2]), "r"(a[3]), "r"(b[0]), "r"(b[1]));
}
__device__ __forceinline__ void split2h(float2 v, uint32_t& hi, uint32_t& lo) {
    __half2 h = __float22half2_rn(v);
    float2 hv = __half22float2(h);
    __half2 l = __float22half2_rn(make_float2(v.x - hv.x, v.y - hv.y));
    hi = *reinterpret_cast<uint32_t*>(&h);
    lo = *reinterpret_cast<uint32_t*>(&l);
}
__device__ __forceinline__ uint32_t packh2(float a, float b) {
    __half2 h = __float22half2_rn(make_float2(a, b));
    return *reinterpret_cast<uint32_t*>(&h);
}

// Per-block idx-dtype detection (int32 read as int64 -> >= 2^32 a.s.)
__device__ __forceinline__ int detect_idx64_block(const void* eidx) {
    __shared__ int s_idx64;
    if (threadIdx.x < 32) {
        const long long* p = (const long long*)eidx;
        int ok = 1;
        #pragma unroll
        for (int i = 0; i < 16; ++i) {
            long long v = p[threadIdx.x * 16 + i];
            ok &= (v >= 0 && v < (long long)N_NODES);
        }
        unsigned m = __ballot_sync(0xffffffffu, ok);
        if (threadIdx.x == 0) s_idx64 = (m == 0xffffffffu) ? 1 : 0;
    }
    __syncthreads();
    return s_idx64;
}

// ---------------------------------------------------------------------------
// CSR build
// ---------------------------------------------------------------------------
__global__ __launch_bounds__(256)
void count_kernel(const void* __restrict__ eidx) {
    const int idx64 = detect_idx64_block(eidx);
    const int e = blockIdx.x * blockDim.x + threadIdx.x;
    if (e >= N_EDGES) return;
    int dst;
    if (idx64) dst = (int)((const long long*)eidx)[N_EDGES + e];
    else       dst = ((const int*)eidx)[N_EDGES + e];
    atomicAdd(&g_cnt[dst], 1);
}

// ---------------------------------------------------------------------------
// scanW: block 0 scans; blocks 1..13 compute weight pre-products.
//   g_Upk[(ktg*128 + n)*4 + tq] = {h(k0,k0+1), h(k0+8,k0+9)},
//   k0 = (ktg%8)*16 + 2*tq, seg = ktg/8 -> U1/U2/U3.
// ---------------------------------------------------------------------------
#define SCAN_T 1024
#define SCAN_CH 49
#define WEIGHT_ITEMS (128 * 96 + 128)   // 12416

__global__ __launch_bounds__(SCAN_T)
void scanW_kernel(const float* __restrict__ Wl1,
                  const float* __restrict__ Wr1,
                  const float* __restrict__ Wl2,
                  const float* __restrict__ Wr2,
                  const float* __restrict__ b1,
                  const float* __restrict__ b2) {
    if (blockIdx.x == 0) {
        __shared__ int wsum[32];
        const int t = threadIdx.x;
        const int base = t * SCAN_CH;

        int cnt[SCAN_CH];
        int lsum = 0;
        #pragma unroll 7
        for (int i = 0; i < SCAN_CH; ++i) {
            const int idx = base + i;
            cnt[i] = (idx < N_NODES) ? g_cnt[idx] : 0;
            lsum += cnt[i];
        }

        int v = lsum;
        #pragma unroll
        for (int d = 1; d < 32; d <<= 1) {
            int n = __shfl_up_sync(0xffffffffu, v, d);
            if ((t & 31) >= d) v += n;
        }
        if ((t & 31) == 31) wsum[t >> 5] = v;
        __syncthreads();
        if (t < 32) {
            int w = wsum[t];
            #pragma unroll
            for (int d = 1; d < 32; d <<= 1) {
                int n = __shfl_up_sync(0xffffffffu, w, d);
                if (t >= d) w += n;
            }
            wsum[t] = w;
        }
        __syncthreads();
        int run = v + ((t >= 32) ? wsum[(t >> 5) - 1] : 0) - lsum;

        #pragma unroll 7
        for (int i = 0; i < SCAN_CH; ++i) {
            const int idx = base + i;
            if (idx < N_NODES) {
                const int c = cnt[i];
                g_rowoff[idx] = run;
                g_cursor[idx] = run;
                g_invdeg[idx] = 1.0f / fmaxf((float)c, 1.0f);
                g_flag[idx]   = (c > 0) ? 1.0f : 0.0f;
                g_cnt[idx]    = 0;   // self-clean for next replay
                run += c;
            }
        }
        if (t == SCAN_T - 1) g_rowoff[N_NODES] = N_EDGES;
        return;
    }

    // ---- weight blocks ----
    const int tid = (blockIdx.x - 1) * SCAN_T + threadIdx.x;
    if (tid < 128 * 96) {
        const int n   = tid / 96;
        const int rem = tid - n * 96;
        const int ktg = rem >> 2;
        const int tq  = rem & 3;
        const int seg = ktg >> 3;
        const int k0  = (ktg & 7) * 16 + 2 * tq;

        float u[4] = {0.f, 0.f, 0.f, 0.f};   // k0, k0+1, k0+8, k0+9
        const float* A1 = Wl2 + (size_t)n * 256;
        const float* A2 = Wr2 + (size_t)n * 256;
        #pragma unroll 4
        for (int t = 0; t < 256; ++t) {
            const float wl2 = A1[t];
            const float wr2 = A2[t];
            const float* rl = Wl1 + (size_t)t * 128 + k0;
            const float* rr = Wr1 + (size_t)t * 128 + k0;
            if (seg == 0) {
                u[0] += wl2 * rl[0]; u[1] += wl2 * rl[1];
                u[2] += wl2 * rl[8]; u[3] += wl2 * rl[9];
            } else if (seg == 1) {
                u[0] += wl2 * rr[0] + wr2 * rl[0];
                u[1] += wl2 * rr[1] + wr2 * rl[1];
                u[2] += wl2 * rr[8] + wr2 * rl[8];
                u[3] += wl2 * rr[9] + wr2 * rl[9];
            } else {
                u[0] += wr2 * rr[0]; u[1] += wr2 * rr[1];
                u[2] += wr2 * rr[8]; u[3] += wr2 * rr[9];
            }
        }
        g_Upk[(ktg * 128 + n) * 4 + tq] =
            make_uint2(packh2(u[0], u[1]), packh2(u[2], u[3]));
    } else if (tid < WEIGHT_ITEMS) {
        const int a = tid - 128 * 96;
        float c = 0.f, d = 0.f;
        #pragma unroll 4
        for (int k = 0; k < 256; ++k) {
            c += Wr2[a * 256 + k] * b1[k];
            d += Wl2[a * 256 + k] * b1[k];
        }
        g_c[a] = b2[a] + c;
        g_d[a] = d;
    }
}

__global__ __launch_bounds__(256)
void fill_csr_kernel(const void* __restrict__ eidx) {
    const int idx64 = detect_idx64_block(eidx);
    const int e = blockIdx.x * blockDim.x + threadIdx.x;
    if (e >= N_EDGES) return;
    int src, dst;
    if (idx64) {
        const long long* ep = (const long long*)eidx;
        src = (int)ep[e]; dst = (int)ep[N_EDGES + e];
    } else {
        const int* ep = (const int*)eidx;
        src = ep[e]; dst = ep[N_EDGES + e];
    }
    const int pos = atomicAdd(&g_cursor[dst], 1);
    g_eadj[pos] = src;
}

// ---------------------------------------------------------------------------
// Gathers: one warp per node, lane owns one float4, unroll 4
// ---------------------------------------------------------------------------
__global__ __launch_bounds__(256)
void gather_kernel(const float* __restrict__ src_feat, float* __restrict__ dst_feat) {
    const int node = (blockIdx.x * blockDim.x + threadIdx.x) >> 5;
    if (node >= N_NODES) return;
    const int lane = threadIdx.x & 31;
    const int beg = g_rowoff[node];
    const int end = g_rowoff[node + 1];
    const float4* f4 = (const float4*)src_feat;

    float4 acc = make_float4(0.f, 0.f, 0.f, 0.f);
    int i = beg;
    for (; i + 4 <= end; i += 4) {
        const int s0 = g_eadj[i];
        const int s1 = g_eadj[i + 1];
        const int s2 = g_eadj[i + 2];
        const int s3 = g_eadj[i + 3];
        float4 v0 = __ldg(&f4[(size_t)s0 * 32 + lane]);
        float4 v1 = __ldg(&f4[(size_t)s1 * 32 + lane]);
        float4 v2 = __ldg(&f4[(size_t)s2 * 32 + lane]);
        float4 v3 = __ldg(&f4[(size_t)s3 * 32 + lane]);
        acc.x += (v0.x + v1.x) + (v2.x + v3.x);
        acc.y += (v0.y + v1.y) + (v2.y + v3.y);
        acc.z += (v0.z + v1.z) + (v2.z + v3.z);
        acc.w += (v0.w + v1.w) + (v2.w + v3.w);
    }
    for (; i < end; ++i) {
        const int s0 = g_eadj[i];
        float4 v0 = __ldg(&f4[(size_t)s0 * 32 + lane]);
        acc.x += v0.x; acc.y += v0.y; acc.z += v0.z; acc.w += v0.w;
    }
    const float w = g_invdeg[node];
    acc.x *= w; acc.y *= w; acc.z *= w; acc.w *= w;
    ((float4*)dst_feat)[(size_t)node * 32 + lane] = acc;
}

// ---------------------------------------------------------------------------
// Tensor-core GEMM: out[M,128] = [A2 | m1 | x] @ U^T + c + flag*d
// A staged per segment: coalesced fp32 loads -> fp16 hi/lo smem tiles;
// fragment fetch via LDS. B frags coalesced global. 4x2 warp layout.
// ---------------------------------------------------------------------------
__global__ __launch_bounds__(256)
void mma_gemm_kernel(const float* __restrict__ x, float* __restrict__ out, int M) {
    extern __shared__ __half sm[];
    __half* sAhi = sm;
    __half* sAlo = sm + SA_HALFS;

    const int tid  = threadIdx.x;
    const int wid  = tid >> 5;
    const int lane = tid & 31;
    const int g    = lane >> 2;
    const int tq   = lane & 3;
    const int m0   = blockIdx.x * 128;
    const int moff = (wid >> 1) * 32;
    const int noff = (wid & 1) * 64;

    int   rows[4];
    bool  rowok[4];
    float flag[4];
    #pragma unroll
    for (int r = 0; r < 4; ++r) {
        const int mi = r >> 1, h = r & 1;
        rows[r]  = m0 + moff + mi * 16 + h * 8 + g;
        rowok[r] = rows[r] < M;
        flag[r]  = rowok[r] ? g_flag[rows[r]] : 0.f;
    }

    float acc[2][8][4];
    #pragma unroll
    for (int mi = 0; mi < 2; ++mi)
        #pragma unroll
        for (int ni = 0; ni < 8; ++ni)
            #pragma unroll
            for (int q = 0; q < 4; ++q) acc[mi][ni][q] = 0.f;

    #pragma unroll 1
    for (int s = 0; s < 3; ++s) {
        const float* Asrc = (s == 0) ? g_A2 : ((s == 1) ? g_m1 : x);

        // ---- stage segment: coalesced fp32 -> fp16 hi/lo smem tiles ----
        if (s > 0) __syncthreads();   // protect previous tiles until consumed
        #pragma unroll 4
        for (int idx = tid; idx < 128 * 32; idx += 256) {
            const int row = idx >> 5;
            const int c4  = (idx & 31) << 2;
            const int node = m0 + row;
            float4 v = make_float4(0.f, 0.f, 0.f, 0.f);
            if (node < M)
                v = *(const float4*)(Asrc + (size_t)node * 128 + c4);
            uint32_t h01, l01, h23, l23;
            split2h(make_float2(v.x, v.y), h01, l01);
            split2h(make_float2(v.z, v.w), h23, l23);
            const int base = row * SA_STRIDE + c4;
            *(uint32_t*)&sAhi[base]     = h01;
            *(uint32_t*)&sAhi[base + 2] = h23;
            *(uint32_t*)&sAlo[base]     = l01;
            *(uint32_t*)&sAlo[base + 2] = l23;
        }
        __syncthreads();

        #pragma unroll 1
        for (int kt = 0; kt < 8; ++kt) {
            const int kk  = kt * 16;
            const int ktg = s * 8 + kt;

            // B fragments: lane-linear coalesced global loads
            uint2 bf[8];
            #pragma unroll
            for (int ni = 0; ni < 8; ++ni) {
                const int n = noff + ni * 8 + g;
                bf[ni] = g_Upk[(ktg * 128 + n) * 4 + tq];
            }

            // A fragments: LDS from staged tiles
            uint32_t ah[2][4], al[2][4];
            #pragma unroll
            for (int mi = 0; mi < 2; ++mi)
                #pragma unroll
                for (int h = 0; h < 2; ++h) {
                    const int srow = moff + mi * 16 + h * 8 + g;
                    #pragma unroll
                    for (int kh = 0; kh < 2; ++kh) {
                        const int off = srow * SA_STRIDE + kk + tq * 2 + kh * 8;
                        ah[mi][kh * 2 + h] = *(const uint32_t*)&sAhi[off];
                        al[mi][kh * 2 + h] = *(const uint32_t*)&sAlo[off];
                    }
                }

            // MMAs: 2 per (mi, ni)
            #pragma unroll
            for (int mi = 0; mi < 2; ++mi)
                #pragma unroll
                for (int ni = 0; ni < 8; ++ni) {
                    uint32_t b2r[2] = {bf[ni].x, bf[ni].y};
                    mma16816h(acc[mi][ni], ah[mi], b2r);
                    mma16816h(acc[mi][ni], al[mi], b2r);
                }
        }
    }

    #pragma unroll
    for (int ni = 0; ni < 8; ++ni) {
        const int col = noff + ni * 8 + tq * 2;
        const float2 cc = *(const float2*)(g_c + col);
        const float2 dd = *(const float2*)(g_d + col);
        #pragma unroll
        for (int mi = 0; mi < 2; ++mi)
            #pragma unroll
            for (int h = 0; h < 2; ++h) {
                const int r = mi * 2 + h;
                if (rowok[r]) {
                    float2 o;
                    o.x = acc[mi][ni][h * 2 + 0] + cc.x + flag[r] * dd.x;
                    o.y = acc[mi][ni][h * 2 + 1] + cc.y + flag[r] * dd.y;
                    *(float2*)(out + (size_t)rows[r] * 128 + col) = o;
                }
            }
    }
}

// ---------------------------------------------------------------------------
// Launch (6 kernels)
// ---------------------------------------------------------------------------
extern "C" void kernel_launch(void* const* d_in, const int* in_sizes, int n_in,
                              void* d_out, int out_size) {
    const float* x    = (const float*)d_in[0];
    const void*  eidx = d_in[1];
    const float* W_l1 = (const float*)d_in[2];
    const float* b_l1 = (const float*)d_in[3];
    const float* W_r1 = (const float*)d_in[4];
    const float* W_l2 = (const float*)d_in[5];
    const float* b_l2 = (const float*)d_in[6];
    const float* W_r2 = (const float*)d_in[7];
    float* out = (float*)d_out;

    float *p_m1, *p_A2;
    cudaGetSymbolAddress((void**)&p_m1, g_m1);
    cudaGetSymbolAddress((void**)&p_A2, g_A2);

    static bool attr_set = false;
    if (!attr_set) {
        cudaFuncSetAttribute(mma_gemm_kernel,
                             cudaFuncAttributeMaxDynamicSharedMemorySize, SMEM_BYTES);
        attr_set = true;
    }

    // 1) count
    count_kernel<<<(N_EDGES + 255) / 256, 256>>>(eidx);
    // 2) scan + weights
    scanW_kernel<<<1 + (WEIGHT_ITEMS + SCAN_T - 1) / SCAN_T, SCAN_T>>>(
        W_l1, W_r1, W_l2, W_r2, b_l1, b_l2);
    // 3) CSR fill
    fill_csr_kernel<<<(N_EDGES + 255) / 256, 256>>>(eidx);
    // 4-5) gathers
    const unsigned gblocks = (N_NODES * 32 + 255) / 256;
    gather_kernel<<<gblocks, 256>>>(x, p_m1);
    gather_kernel<<<gblocks, 256>>>(p_m1, p_A2);
    // 6) fused tensor-core GEMM (A smem-staged)
    mma_gemm_kernel<<<(N_NODES + 127) / 128, 256, SMEM_BYTES>>>(x, out, N_NODES);
}

// round 12
// speedup vs baseline: 1.8209x; 1.1355x over previous
#include <cuda_runtime.h>
#include <cuda_fp16.h>
#include <cstdint>
#include <cstddef>

// Problem constants (match reference)
#define N_NODES 50000
#define N_EDGES 800000
#define D_IN    128
#define D_HID   256
#define D_OUT   128

// ---------------------------------------------------------------------------
// Pipeline (8 launches):
//   count   : dst histogram, 4 edges/thread (inline idx-dtype detect)
//   scanA   : per-block (256-node) sums -> g_bsum
//   scanB   : block 0 scans g_bsum; blocks 1.. compute weight pre-products
//   scanC   : block-local scan -> rowoff/cursor/invdeg/flag; self-clean g_cnt
//   fill    : CSR adjacency, 4 edges/thread
//   gather1 : m1[n] = invdeg[n] * sum x[s]
//   gather2 : A2[n] = invdeg[n] * sum m1[s]
//   gemm    : out = A2@U1^T + m1@U2^T + x@U3^T + c + flag*d
//             (mma.sync fp16 A hi/lo 2-term; A smem-staged; B frags coalesced)
// ---------------------------------------------------------------------------

#define SCAN_BLOCKS ((N_NODES + 255) / 256)   // 196

// Device scratch
__device__ int   g_cnt[N_NODES];          // zero at load; scanC re-zeroes per replay
__device__ int   g_bsum[SCAN_BLOCKS];
__device__ int   g_boff[SCAN_BLOCKS];
__device__ int   g_rowoff[N_NODES + 1];
__device__ int   g_cursor[N_NODES];
__device__ int   g_eadj[N_EDGES];
__device__ float g_invdeg[N_NODES];
__device__ float g_flag[N_NODES];
__device__ float g_m1[(size_t)N_NODES * 128];
__device__ float g_A2[(size_t)N_NODES * 128];
// B fragments, warp-coalesced: index = (ktg*128 + n)*4 + tq
__device__ uint2 g_Upk[24 * 128 * 4];
__device__ float g_c[128];
__device__ float g_d[128];

// smem tile geometry (half): 128 rows x 128 cols, padded stride 132
#define SA_STRIDE 132
#define SA_HALFS  (128 * SA_STRIDE)
#define SMEM_BYTES (2 * SA_HALFS * 2)    // hi + lo tiles = 67584 B

// ---------------------------------------------------------------------------
// mma helpers (fp16 inputs, fp32 accumulate)
// ---------------------------------------------------------------------------
__device__ __forceinline__ void mma16816h(float* d, const uint32_t* a, const uint32_t* b) {
    asm volatile(
        "mma.sync.aligned.m16n8k16.row.col.f32.f16.f16.f32 "
        "{%0,%1,%2,%3}, {%4,%5,%6,%7}, {%8,%9}, {%0,%1,%2,%3};"
        : "+f"(d[0]), "+f"(d[1]), "+f"(d[2]), "+f"(d[3])
        : "r"(a[0]), "r"(a[1]), "r"(a[2]), "r"(a[3]), "r"(b[0]), "r"(b[1]));
}
__device__ __forceinline__ void split2h(float2 v, uint32_t& hi, uint32_t& lo) {
    __half2 h = __float22half2_rn(v);
    float2 hv = __half22float2(h);
    __half2 l = __float22half2_rn(make_float2(v.x - hv.x, v.y - hv.y));
    hi = *reinterpret_cast<uint32_t*>(&h);
    lo = *reinterpret_cast<uint32_t*>(&l);
}
__device__ __forceinline__ uint32_t packh2(float a, float b) {
    __half2 h = __float22half2_rn(make_float2(a, b));
    return *reinterpret_cast<uint32_t*>(&h);
}

// Per-block idx-dtype detection (int32 read as int64 -> >= 2^32 a.s.)
__device__ __forceinline__ int detect_idx64_block(const void* eidx) {
    __shared__ int s_idx64;
    if (threadIdx.x < 32) {
        const long long* p = (const long long*)eidx;
        int ok = 1;
        #pragma unroll
        for (int i = 0; i < 16; ++i) {
            long long v = p[threadIdx.x * 16 + i];
            ok &= (v >= 0 && v < (long long)N_NODES);
        }
        unsigned m = __ballot_sync(0xffffffffu, ok);
        if (threadIdx.x == 0) s_idx64 = (m == 0xffffffffu) ? 1 : 0;
    }
    __syncthreads();
    return s_idx64;
}

// ---------------------------------------------------------------------------
// count: dst histogram, 4 edges per thread
// ---------------------------------------------------------------------------
__global__ __launch_bounds__(256)
void count_kernel(const void* __restrict__ eidx) {
    const int idx64 = detect_idx64_block(eidx);
    const int e0 = (blockIdx.x * blockDim.x + threadIdx.x) * 4;
    if (e0 >= N_EDGES) return;
    int d[4];
    const int nv = min(4, N_EDGES - e0);
    if (idx64) {
        const longlong2* p = (const longlong2*)((const long long*)eidx + N_EDGES + e0);
        longlong2 a = p[0];
        longlong2 b = (nv > 2) ? p[1] : make_longlong2(0, 0);
        d[0] = (int)a.x; d[1] = (int)a.y; d[2] = (int)b.x; d[3] = (int)b.y;
    } else {
        const int4 a = *(const int4*)((const int*)eidx + N_EDGES + e0);
        d[0] = a.x; d[1] = a.y; d[2] = a.z; d[3] = a.w;
    }
    #pragma unroll
    for (int j = 0; j < 4; ++j)
        if (j < nv) atomicAdd(&g_cnt[d[j]], 1);
}

// ---------------------------------------------------------------------------
// scanA: per-block sums of 256 counts
// ---------------------------------------------------------------------------
__global__ __launch_bounds__(256)
void scanA_kernel() {
    __shared__ int ws[8];
    const int node = blockIdx.x * 256 + threadIdx.x;
    int v = (node < N_NODES) ? g_cnt[node] : 0;
    #pragma unroll
    for (int d = 16; d > 0; d >>= 1) v += __shfl_down_sync(0xffffffffu, v, d);
    if ((threadIdx.x & 31) == 0) ws[threadIdx.x >> 5] = v;
    __syncthreads();
    if (threadIdx.x < 8) {
        int s = ws[threadIdx.x];
        #pragma unroll
        for (int d = 4; d > 0; d >>= 1) s += __shfl_down_sync(0xffu, s, d);
        if (threadIdx.x == 0) g_bsum[blockIdx.x] = s;
    }
}

// ---------------------------------------------------------------------------
// scanB: block 0 = exclusive scan of g_bsum (196 entries, smem Hillis-Steele);
//        blocks 1.. = weight pre-products.
//   g_Upk[(ktg*128 + n)*4 + tq] = {h(k0,k0+1), h(k0+8,k0+9)},
//   k0 = (ktg%8)*16 + 2*tq, seg = ktg/8 -> U1/U2/U3.
// ---------------------------------------------------------------------------
#define WEIGHT_ITEMS (128 * 96 + 128)   // 12416
#define WEIGHT_BLOCKS ((WEIGHT_ITEMS + 255) / 256)   // 49

__global__ __launch_bounds__(256)
void scanB_kernel(const float* __restrict__ Wl1,
                  const float* __restrict__ Wr1,
                  const float* __restrict__ Wl2,
                  const float* __restrict__ Wr2,
                  const float* __restrict__ b1,
                  const float* __restrict__ b2) {
    if (blockIdx.x == 0) {
        __shared__ int sc[256];
        const int t = threadIdx.x;
        sc[t] = (t < SCAN_BLOCKS) ? g_bsum[t] : 0;
        __syncthreads();
        // inclusive Hillis-Steele
        #pragma unroll
        for (int d = 1; d < 256; d <<= 1) {
            int add = (t >= d) ? sc[t - d] : 0;
            __syncthreads();
            sc[t] += add;
            __syncthreads();
        }
        if (t < SCAN_BLOCKS) g_boff[t] = sc[t] - g_bsum[t];   // exclusive
        return;
    }

    const int tid = (blockIdx.x - 1) * 256 + threadIdx.x;
    if (tid < 128 * 96) {
        const int n   = tid / 96;
        const int rem = tid - n * 96;
        const int ktg = rem >> 2;
        const int tq  = rem & 3;
        const int seg = ktg >> 3;
        const int k0  = (ktg & 7) * 16 + 2 * tq;

        float u[4] = {0.f, 0.f, 0.f, 0.f};   // k0, k0+1, k0+8, k0+9
        const float* A1 = Wl2 + (size_t)n * 256;
        const float* A2 = Wr2 + (size_t)n * 256;
        #pragma unroll 4
        for (int t = 0; t < 256; ++t) {
            const float wl2 = A1[t];
            const float wr2 = A2[t];
            const float* rl = Wl1 + (size_t)t * 128 + k0;
            const float* rr = Wr1 + (size_t)t * 128 + k0;
            if (seg == 0) {
                u[0] += wl2 * rl[0]; u[1] += wl2 * rl[1];
                u[2] += wl2 * rl[8]; u[3] += wl2 * rl[9];
            } else if (seg == 1) {
                u[0] += wl2 * rr[0] + wr2 * rl[0];
                u[1] += wl2 * rr[1] + wr2 * rl[1];
                u[2] += wl2 * rr[8] + wr2 * rl[8];
                u[3] += wl2 * rr[9] + wr2 * rl[9];
            } else {
                u[0] += wr2 * rr[0]; u[1] += wr2 * rr[1];
                u[2] += wr2 * rr[8]; u[3] += wr2 * rr[9];
            }
        }
        g_Upk[(ktg * 128 + n) * 4 + tq] =
            make_uint2(packh2(u[0], u[1]), packh2(u[2], u[3]));
    } else if (tid < WEIGHT_ITEMS) {
        const int a = tid - 128 * 96;
        float c = 0.f, d = 0.f;
        #pragma unroll 4
        for (int k = 0; k < 256; ++k) {
            c += Wr2[a * 256 + k] * b1[k];
            d += Wl2[a * 256 + k] * b1[k];
        }
        g_c[a] = b2[a] + c;
        g_d[a] = d;
    }
}

// ---------------------------------------------------------------------------
// scanC: block-local exclusive scan + write rowoff/cursor/invdeg/flag,
//        self-clean g_cnt.
// ---------------------------------------------------------------------------
__global__ __launch_bounds__(256)
void scanC_kernel() {
    __shared__ int sc[256];
    const int t = threadIdx.x;
    const int node = blockIdx.x * 256 + t;
    const int c = (node < N_NODES) ? g_cnt[node] : 0;
    sc[t] = c;
    __syncthreads();
    #pragma unroll
    for (int d = 1; d < 256; d <<= 1) {
        int add = (t >= d) ? sc[t - d] : 0;
        __syncthreads();
        sc[t] += add;
        __syncthreads();
    }
    if (node < N_NODES) {
        const int off = g_boff[blockIdx.x] + sc[t] - c;   // exclusive
        g_rowoff[node] = off;
        g_cursor[node] = off;
        g_invdeg[node] = 1.0f / fmaxf((float)c, 1.0f);
        g_flag[node]   = (c > 0) ? 1.0f : 0.0f;
        g_cnt[node]    = 0;   // self-clean for next replay
    }
    if (node == N_NODES - 1) g_rowoff[N_NODES] = N_EDGES;
}

// ---------------------------------------------------------------------------
// fill: CSR adjacency, 4 edges per thread
// ---------------------------------------------------------------------------
__global__ __launch_bounds__(256)
void fill_csr_kernel(const void* __restrict__ eidx) {
    const int idx64 = detect_idx64_block(eidx);
    const int e0 = (blockIdx.x * blockDim.x + threadIdx.x) * 4;
    if (e0 >= N_EDGES) return;
    const int nv = min(4, N_EDGES - e0);
    int s[4], d[4];
    if (idx64) {
        const long long* ep = (const long long*)eidx;
        const longlong2* ps = (const longlong2*)(ep + e0);
        const longlong2* pd = (const longlong2*)(ep + N_EDGES + e0);
        longlong2 sa = ps[0];
        longlong2 sb = (nv > 2) ? ps[1] : make_longlong2(0, 0);
        longlong2 da = pd[0];
        longlong2 db = (nv > 2) ? pd[1] : make_longlong2(0, 0);
        s[0] = (int)sa.x; s[1] = (int)sa.y; s[2] = (int)sb.x; s[3] = (int)sb.y;
        d[0] = (int)da.x; d[1] = (int)da.y; d[2] = (int)db.x; d[3] = (int)db.y;
    } else {
        const int* ep = (const int*)eidx;
        const int4 sa = *(const int4*)(ep + e0);
        const int4 da = *(const int4*)(ep + N_EDGES + e0);
        s[0] = sa.x; s[1] = sa.y; s[2] = sa.z; s[3] = sa.w;
        d[0] = da.x; d[1] = da.y; d[2] = da.z; d[3] = da.w;
    }
    #pragma unroll
    for (int j = 0; j < 4; ++j)
        if (j < nv) {
            const int pos = atomicAdd(&g_cursor[d[j]], 1);
            g_eadj[pos] = s[j];
        }
}

// ---------------------------------------------------------------------------
// Gathers: one warp per node, lane owns one float4, unroll 4
// ---------------------------------------------------------------------------
__global__ __launch_bounds__(256)
void gather_kernel(const float* __restrict__ src_feat, float* __restrict__ dst_feat) {
    const int node = (blockIdx.x * blockDim.x + threadIdx.x) >> 5;
    if (node >= N_NODES) return;
    const int lane = threadIdx.x & 31;
    const int beg = g_rowoff[node];
    const int end = g_rowoff[node + 1];
    const float4* f4 = (const float4*)src_feat;

    float4 acc = make_float4(0.f, 0.f, 0.f, 0.f);
    int i = beg;
    for (; i + 4 <= end; i += 4) {
        const int s0 = g_eadj[i];
        const int s1 = g_eadj[i + 1];
        const int s2 = g_eadj[i + 2];
        const int s3 = g_eadj[i + 3];
        float4 v0 = __ldg(&f4[(size_t)s0 * 32 + lane]);
        float4 v1 = __ldg(&f4[(size_t)s1 * 32 + lane]);
        float4 v2 = __ldg(&f4[(size_t)s2 * 32 + lane]);
        float4 v3 = __ldg(&f4[(size_t)s3 * 32 + lane]);
        acc.x += (v0.x + v1.x) + (v2.x + v3.x);
        acc.y += (v0.y + v1.y) + (v2.y + v3.y);
        acc.z += (v0.z + v1.z) + (v2.z + v3.z);
        acc.w += (v0.w + v1.w) + (v2.w + v3.w);
    }
    for (; i < end; ++i) {
        const int s0 = g_eadj[i];
        float4 v0 = __ldg(&f4[(size_t)s0 * 32 + lane]);
        acc.x += v0.x; acc.y += v0.y; acc.z += v0.z; acc.w += v0.w;
    }
    const float w = g_invdeg[node];
    acc.x *= w; acc.y *= w; acc.z *= w; acc.w *= w;
    ((float4*)dst_feat)[(size_t)node * 32 + lane] = acc;
}

// ---------------------------------------------------------------------------
// Tensor-core GEMM: out[M,128] = [A2 | m1 | x] @ U^T + c + flag*d
// A staged per segment (coalesced fp32 -> fp16 hi/lo smem); B frags coalesced.
// ---------------------------------------------------------------------------
__global__ __launch_bounds__(256)
void mma_gemm_kernel(const float* __restrict__ x, float* __restrict__ out, int M) {
    extern __shared__ __half sm[];
    __half* sAhi = sm;
    __half* sAlo = sm + SA_HALFS;

    const int tid  = threadIdx.x;
    const int wid  = tid >> 5;
    const int lane = tid & 31;
    const int g    = lane >> 2;
    const int tq   = lane & 3;
    const int m0   = blockIdx.x * 128;
    const int moff = (wid >> 1) * 32;
    const int noff = (wid & 1) * 64;

    int   rows[4];
    bool  rowok[4];
    float flag[4];
    #pragma unroll
    for (int r = 0; r < 4; ++r) {
        const int mi = r >> 1, h = r & 1;
        rows[r]  = m0 + moff + mi * 16 + h * 8 + g;
        rowok[r] = rows[r] < M;
        flag[r]  = rowok[r] ? g_flag[rows[r]] : 0.f;
    }

    float acc[2][8][4];
    #pragma unroll
    for (int mi = 0; mi < 2; ++mi)
        #pragma unroll
        for (int ni = 0; ni < 8; ++ni)
            #pragma unroll
            for (int q = 0; q < 4; ++q) acc[mi][ni][q] = 0.f;

    #pragma unroll 1
    for (int s = 0; s < 3; ++s) {
        const float* Asrc = (s == 0) ? g_A2 : ((s == 1) ? g_m1 : x);

        if (s > 0) __syncthreads();
        #pragma unroll 4
        for (int idx = tid; idx < 128 * 32; idx += 256) {
            const int row = idx >> 5;
            const int c4  = (idx & 31) << 2;
            const int node = m0 + row;
            float4 v = make_float4(0.f, 0.f, 0.f, 0.f);
            if (node < M)
                v = *(const float4*)(Asrc + (size_t)node * 128 + c4);
            uint32_t h01, l01, h23, l23;
            split2h(make_float2(v.x, v.y), h01, l01);
            split2h(make_float2(v.z, v.w), h23, l23);
            const int base = row * SA_STRIDE + c4;
            *(uint32_t*)&sAhi[base]     = h01;
            *(uint32_t*)&sAhi[base + 2] = h23;
            *(uint32_t*)&sAlo[base]     = l01;
            *(uint32_t*)&sAlo[base + 2] = l23;
        }
        __syncthreads();

        #pragma unroll 1
        for (int kt = 0; kt < 8; ++kt) {
            const int kk  = kt * 16;
            const int ktg = s * 8 + kt;

            uint2 bf[8];
            #pragma unroll
            for (int ni = 0; ni < 8; ++ni) {
                const int n = noff + ni * 8 + g;
                bf[ni] = g_Upk[(ktg * 128 + n) * 4 + tq];
            }

            uint32_t ah[2][4], al[2][4];
            #pragma unroll
            for (int mi = 0; mi < 2; ++mi)
                #pragma unroll
                for (int h = 0; h < 2; ++h) {
                    const int srow = moff + mi * 16 + h * 8 + g;
                    #pragma unroll
                    for (int kh = 0; kh < 2; ++kh) {
                        const int off = srow * SA_STRIDE + kk + tq * 2 + kh * 8;
                        ah[mi][kh * 2 + h] = *(const uint32_t*)&sAhi[off];
                        al[mi][kh * 2 + h] = *(const uint32_t*)&sAlo[off];
                    }
                }

            #pragma unroll
            for (int mi = 0; mi < 2; ++mi)
                #pragma unroll
                for (int ni = 0; ni < 8; ++ni) {
                    uint32_t b2r[2] = {bf[ni].x, bf[ni].y};
                    mma16816h(acc[mi][ni], ah[mi], b2r);
                    mma16816h(acc[mi][ni], al[mi], b2r);
                }
        }
    }

    #pragma unroll
    for (int ni = 0; ni < 8; ++ni) {
        const int col = noff + ni * 8 + tq * 2;
        const float2 cc = *(const float2*)(g_c + col);
        const float2 dd = *(const float2*)(g_d + col);
        #pragma unroll
        for (int mi = 0; mi < 2; ++mi)
            #pragma unroll
            for (int h = 0; h < 2; ++h) {
                const int r = mi * 2 + h;
                if (rowok[r]) {
                    float2 o;
                    o.x = acc[mi][ni][h * 2 + 0] + cc.x + flag[r] * dd.x;
                    o.y = acc[mi][ni][h * 2 + 1] + cc.y + flag[r] * dd.y;
                    *(float2*)(out + (size_t)rows[r] * 128 + col) = o;
                }
            }
    }
}

// ---------------------------------------------------------------------------
// Launch (8 kernels)
// ---------------------------------------------------------------------------
extern "C" void kernel_launch(void* const* d_in, const int* in_sizes, int n_in,
                              void* d_out, int out_size) {
    const float* x    = (const float*)d_in[0];
    const void*  eidx = d_in[1];
    const float* W_l1 = (const float*)d_in[2];
    const float* b_l1 = (const float*)d_in[3];
    const float* W_r1 = (const float*)d_in[4];
    const float* W_l2 = (const float*)d_in[5];
    const float* b_l2 = (const float*)d_in[6];
    const float* W_r2 = (const float*)d_in[7];
    float* out = (float*)d_out;

    float *p_m1, *p_A2;
    cudaGetSymbolAddress((void**)&p_m1, g_m1);
    cudaGetSymbolAddress((void**)&p_A2, g_A2);

    static bool attr_set = false;
    if (!attr_set) {
        cudaFuncSetAttribute(mma_gemm_kernel,
                             cudaFuncAttributeMaxDynamicSharedMemorySize, SMEM_BYTES);
        attr_set = true;
    }

    // 1) count (4 edges/thread)
    count_kernel<<<(N_EDGES / 4 + 255) / 256, 256>>>(eidx);
    // 2) scanA: block sums
    scanA_kernel<<<SCAN_BLOCKS, 256>>>();
    // 3) scanB: scan of block sums + weight pre-products
    scanB_kernel<<<1 + WEIGHT_BLOCKS, 256>>>(W_l1, W_r1, W_l2, W_r2, b_l1, b_l2);
    // 4) scanC: per-node offsets (profiled slot)
    scanC_kernel<<<SCAN_BLOCKS, 256>>>();
    // 5) fill (4 edges/thread)
    fill_csr_kernel<<<(N_EDGES / 4 + 255) / 256, 256>>>(eidx);
    // 6-7) gathers
    const unsigned gblocks = (N_NODES * 32 + 255) / 256;
    gather_kernel<<<gblocks, 256>>>(x, p_m1);
    gather_kernel<<<gblocks, 256>>>(p_m1, p_A2);
    // 8) fused tensor-core GEMM (A smem-staged)
    mma_gemm_kernel<<<(N_NODES + 127) / 128, 256, SMEM_BYTES>>>(x, out, N_NODES);
}

// round 13
// speedup vs baseline: 1.9800x; 1.0873x over previous
#include <cuda_runtime.h>
#include <cuda_fp16.h>
#include <cstdint>
#include <cstddef>

// Problem constants (match reference)
#define N_NODES 50000
#define N_EDGES 800000
#define D_IN    128
#define D_HID   256
#define D_OUT   128

// ---------------------------------------------------------------------------
// Pipeline (8 launches; all node features fp16 after conversion):
//   count+conv : dst histogram (4 edges/thr) + x -> fp16 g_xh
//   scanA      : per-block (256-node) sums -> g_bsum
//   scanB      : block 0 scans g_bsum; blocks 1.. weight pre-products (fp16 U)
//   scanC      : block-local scan -> rowoff/cursor/invdeg/flag; self-clean cnt
//   fill       : CSR adjacency, 4 edges/thread
//   gather1    : m1h[n] = fp16( invdeg[n] * sum xh[s] )     (fp32 accum)
//   gather2    : A2h[n] = fp16( invdeg[n] * sum m1h[s] )
//   gemm       : out = A2h@U1^T + m1h@U2^T + xh@U3^T + c + flag*d
//                (mma.sync fp16, single-term; A smem-staged; B frags coalesced)
// ---------------------------------------------------------------------------

#define SCAN_BLOCKS ((N_NODES + 255) / 256)   // 196

// Device scratch
__device__ int    g_cnt[N_NODES];         // zero at load; scanC re-zeroes per replay
__device__ int    g_bsum[SCAN_BLOCKS];
__device__ int    g_boff[SCAN_BLOCKS];
__device__ int    g_rowoff[N_NODES + 1];
__device__ int    g_cursor[N_NODES];
__device__ int    g_eadj[N_EDGES];
__device__ float  g_invdeg[N_NODES];
__device__ float  g_flag[N_NODES];
__device__ __half g_xh[(size_t)N_NODES * 128];
__device__ __half g_m1h[(size_t)N_NODES * 128];
__device__ __half g_A2h[(size_t)N_NODES * 128];
// B fragments, warp-coalesced: index = (ktg*128 + n)*4 + tq
__device__ uint2  g_Upk[24 * 128 * 4];
__device__ float  g_c[128];
__device__ float  g_d[128];

// smem tile geometry (half): 128 rows x 128 cols, stride 136 (16B-aligned rows,
// conflict-free fragment reads: row step = 68 words = 4 banks)
#define SA_STRIDE 136
#define SMEM_BYTES (128 * SA_STRIDE * 2)   // 34816 B

// ---------------------------------------------------------------------------
// helpers
// ---------------------------------------------------------------------------
__device__ __forceinline__ void mma16816h(float* d, const uint32_t* a, const uint32_t* b) {
    asm volatile(
        "mma.sync.aligned.m16n8k16.row.col.f32.f16.f16.f32 "
        "{%0,%1,%2,%3}, {%4,%5,%6,%7}, {%8,%9}, {%0,%1,%2,%3};"
        : "+f"(d[0]), "+f"(d[1]), "+f"(d[2]), "+f"(d[3])
        : "r"(a[0]), "r"(a[1]), "r"(a[2]), "r"(a[3]), "r"(b[0]), "r"(b[1]));
}
__device__ __forceinline__ uint32_t packh2(float a, float b) {
    __half2 h = __float22half2_rn(make_float2(a, b));
    return *reinterpret_cast<uint32_t*>(&h);
}
__device__ __forceinline__ float2 unpackh2(uint32_t u) {
    __half2 h = *reinterpret_cast<__half2*>(&u);
    return __half22float2(h);
}

// Per-block idx-dtype detection (int32 read as int64 -> >= 2^32 a.s.)
__device__ __forceinline__ int detect_idx64_block(const void* eidx) {
    __shared__ int s_idx64;
    if (threadIdx.x < 32) {
        const long long* p = (const long long*)eidx;
        int ok = 1;
        #pragma unroll
        for (int i = 0; i < 16; ++i) {
            long long v = p[threadIdx.x * 16 + i];
            ok &= (v >= 0 && v < (long long)N_NODES);
        }
        unsigned m = __ballot_sync(0xffffffffu, ok);
        if (threadIdx.x == 0) s_idx64 = (m == 0xffffffffu) ? 1 : 0;
    }
    __syncthreads();
    return s_idx64;
}

// ---------------------------------------------------------------------------
// count + convert: 3125 blocks. Every block converts 2 float4-groups/thread
// of x -> fp16; blocks 0..781 also histogram 4 edges/thread.
// ---------------------------------------------------------------------------
#define CONV_BLOCKS 3125   // 1.6M float4 groups / (256 thr * 2)
#define EDGE_BLOCKS ((N_EDGES / 4 + 255) / 256)   // 782

__global__ __launch_bounds__(256)
void count_conv_kernel(const void* __restrict__ eidx, const float* __restrict__ x) {
    const int idx64 = detect_idx64_block(eidx);
    const int tid = blockIdx.x * 256 + threadIdx.x;

    // convert: 1.6M float4 groups total, 2 per thread
    const float4* x4 = (const float4*)x;
    #pragma unroll
    for (int j = 0; j < 2; ++j) {
        const int gidx = tid + j * (CONV_BLOCKS * 256);
        if (gidx < (N_NODES * 128) / 4) {
            float4 v = x4[gidx];
            uint2 h;
            h.x = packh2(v.x, v.y);
            h.y = packh2(v.z, v.w);
            ((uint2*)g_xh)[gidx] = h;
        }
    }

    // histogram
    if (blockIdx.x < EDGE_BLOCKS) {
        const int e0 = tid * 4;
        if (e0 < N_EDGES) {
            int d[4];
            const int nv = min(4, N_EDGES - e0);
            if (idx64) {
                const longlong2* p = (const longlong2*)((const long long*)eidx + N_EDGES + e0);
                longlong2 a = p[0];
                longlong2 b = (nv > 2) ? p[1] : make_longlong2(0, 0);
                d[0] = (int)a.x; d[1] = (int)a.y; d[2] = (int)b.x; d[3] = (int)b.y;
            } else {
                const int4 a = *(const int4*)((const int*)eidx + N_EDGES + e0);
                d[0] = a.x; d[1] = a.y; d[2] = a.z; d[3] = a.w;
            }
            #pragma unroll
            for (int j = 0; j < 4; ++j)
                if (j < nv) atomicAdd(&g_cnt[d[j]], 1);
        }
    }
}

// ---------------------------------------------------------------------------
// scanA: per-block sums of 256 counts
// ---------------------------------------------------------------------------
__global__ __launch_bounds__(256)
void scanA_kernel() {
    __shared__ int ws[8];
    const int node = blockIdx.x * 256 + threadIdx.x;
    int v = (node < N_NODES) ? g_cnt[node] : 0;
    #pragma unroll
    for (int d = 16; d > 0; d >>= 1) v += __shfl_down_sync(0xffffffffu, v, d);
    if ((threadIdx.x & 31) == 0) ws[threadIdx.x >> 5] = v;
    __syncthreads();
    if (threadIdx.x < 8) {
        int s = ws[threadIdx.x];
        #pragma unroll
        for (int d = 4; d > 0; d >>= 1) s += __shfl_down_sync(0xffu, s, d);
        if (threadIdx.x == 0) g_bsum[blockIdx.x] = s;
    }
}

// ---------------------------------------------------------------------------
// scanB: block 0 = exclusive scan of g_bsum; blocks 1.. = weight pre-products
//   g_Upk[(ktg*128 + n)*4 + tq] = {h(k0,k0+1), h(k0+8,k0+9)},
//   k0 = (ktg%8)*16 + 2*tq, seg = ktg/8 -> U1/U2/U3.
// ---------------------------------------------------------------------------
#define WEIGHT_ITEMS (128 * 96 + 128)                  // 12416
#define WEIGHT_BLOCKS ((WEIGHT_ITEMS + 255) / 256)     // 49

__global__ __launch_bounds__(256)
void scanB_kernel(const float* __restrict__ Wl1,
                  const float* __restrict__ Wr1,
                  const float* __restrict__ Wl2,
                  const float* __restrict__ Wr2,
                  const float* __restrict__ b1,
                  const float* __restrict__ b2) {
    if (blockIdx.x == 0) {
        __shared__ int sc[256];
        const int t = threadIdx.x;
        sc[t] = (t < SCAN_BLOCKS) ? g_bsum[t] : 0;
        __syncthreads();
        #pragma unroll
        for (int d = 1; d < 256; d <<= 1) {
            int add = (t >= d) ? sc[t - d] : 0;
            __syncthreads();
            sc[t] += add;
            __syncthreads();
        }
        if (t < SCAN_BLOCKS) g_boff[t] = sc[t] - g_bsum[t];
        return;
    }

    const int tid = (blockIdx.x - 1) * 256 + threadIdx.x;
    if (tid < 128 * 96) {
        const int n   = tid / 96;
        const int rem = tid - n * 96;
        const int ktg = rem >> 2;
        const int tq  = rem & 3;
        const int seg = ktg >> 3;
        const int k0  = (ktg & 7) * 16 + 2 * tq;

        float u[4] = {0.f, 0.f, 0.f, 0.f};
        const float* A1 = Wl2 + (size_t)n * 256;
        const float* A2 = Wr2 + (size_t)n * 256;
        #pragma unroll 4
        for (int t = 0; t < 256; ++t) {
            const float wl2 = A1[t];
            const float wr2 = A2[t];
            const float* rl = Wl1 + (size_t)t * 128 + k0;
            const float* rr = Wr1 + (size_t)t * 128 + k0;
            if (seg == 0) {
                u[0] += wl2 * rl[0]; u[1] += wl2 * rl[1];
                u[2] += wl2 * rl[8]; u[3] += wl2 * rl[9];
            } else if (seg == 1) {
                u[0] += wl2 * rr[0] + wr2 * rl[0];
                u[1] += wl2 * rr[1] + wr2 * rl[1];
                u[2] += wl2 * rr[8] + wr2 * rl[8];
                u[3] += wl2 * rr[9] + wr2 * rl[9];
            } else {
                u[0] += wr2 * rr[0]; u[1] += wr2 * rr[1];
                u[2] += wr2 * rr[8]; u[3] += wr2 * rr[9];
            }
        }
        g_Upk[(ktg * 128 + n) * 4 + tq] =
            make_uint2(packh2(u[0], u[1]), packh2(u[2], u[3]));
    } else if (tid < WEIGHT_ITEMS) {
        const int a = tid - 128 * 96;
        float c = 0.f, d = 0.f;
        #pragma unroll 4
        for (int k = 0; k < 256; ++k) {
            c += Wr2[a * 256 + k] * b1[k];
            d += Wl2[a * 256 + k] * b1[k];
        }
        g_c[a] = b2[a] + c;
        g_d[a] = d;
    }
}

// ---------------------------------------------------------------------------
// scanC: block-local exclusive scan + metadata; self-clean g_cnt
// ---------------------------------------------------------------------------
__global__ __launch_bounds__(256)
void scanC_kernel() {
    __shared__ int sc[256];
    const int t = threadIdx.x;
    const int node = blockIdx.x * 256 + t;
    const int c = (node < N_NODES) ? g_cnt[node] : 0;
    sc[t] = c;
    __syncthreads();
    #pragma unroll
    for (int d = 1; d < 256; d <<= 1) {
        int add = (t >= d) ? sc[t - d] : 0;
        __syncthreads();
        sc[t] += add;
        __syncthreads();
    }
    if (node < N_NODES) {
        const int off = g_boff[blockIdx.x] + sc[t] - c;
        g_rowoff[node] = off;
        g_cursor[node] = off;
        g_invdeg[node] = 1.0f / fmaxf((float)c, 1.0f);
        g_flag[node]   = (c > 0) ? 1.0f : 0.0f;
        g_cnt[node]    = 0;
    }
    if (node == N_NODES - 1) g_rowoff[N_NODES] = N_EDGES;
}

// ---------------------------------------------------------------------------
// fill: CSR adjacency, 4 edges per thread
// ---------------------------------------------------------------------------
__global__ __launch_bounds__(256)
void fill_csr_kernel(const void* __restrict__ eidx) {
    const int idx64 = detect_idx64_block(eidx);
    const int e0 = (blockIdx.x * blockDim.x + threadIdx.x) * 4;
    if (e0 >= N_EDGES) return;
    const int nv = min(4, N_EDGES - e0);
    int s[4], d[4];
    if (idx64) {
        const long long* ep = (const long long*)eidx;
        const longlong2* ps = (const longlong2*)(ep + e0);
        const longlong2* pd = (const longlong2*)(ep + N_EDGES + e0);
        longlong2 sa = ps[0];
        longlong2 sb = (nv > 2) ? ps[1] : make_longlong2(0, 0);
        longlong2 da = pd[0];
        longlong2 db = (nv > 2) ? pd[1] : make_longlong2(0, 0);
        s[0] = (int)sa.x; s[1] = (int)sa.y; s[2] = (int)sb.x; s[3] = (int)sb.y;
        d[0] = (int)da.x; d[1] = (int)da.y; d[2] = (int)db.x; d[3] = (int)db.y;
    } else {
        const int* ep = (const int*)eidx;
        const int4 sa = *(const int4*)(ep + e0);
        const int4 da = *(const int4*)(ep + N_EDGES + e0);
        s[0] = sa.x; s[1] = sa.y; s[2] = sa.z; s[3] = sa.w;
        d[0] = da.x; d[1] = da.y; d[2] = da.z; d[3] = da.w;
    }
    #pragma unroll
    for (int j = 0; j < 4; ++j)
        if (j < nv) {
            const int pos = atomicAdd(&g_cursor[d[j]], 1);
            g_eadj[pos] = s[j];
        }
}

// ---------------------------------------------------------------------------
// Gather (fp16 in/out, fp32 accum): one warp per node, lane owns 4 columns
// (one uint2 = 4 halves per row), unroll 4 edges.
// ---------------------------------------------------------------------------
__global__ __launch_bounds__(256)
void gather_kernel(const __half* __restrict__ src_feat, __half* __restrict__ dst_feat) {
    const int node = (blockIdx.x * blockDim.x + threadIdx.x) >> 5;
    if (node >= N_NODES) return;
    const int lane = threadIdx.x & 31;
    const int beg = g_rowoff[node];
    const int end = g_rowoff[node + 1];
    const uint2* f2 = (const uint2*)src_feat;   // 32 uint2 per row

    float4 acc = make_float4(0.f, 0.f, 0.f, 0.f);
    int i = beg;
    for (; i + 4 <= end; i += 4) {
        const int s0 = g_eadj[i];
        const int s1 = g_eadj[i + 1];
        const int s2 = g_eadj[i + 2];
        const int s3 = g_eadj[i + 3];
        uint2 u0 = __ldg(&f2[(size_t)s0 * 32 + lane]);
        uint2 u1 = __ldg(&f2[(size_t)s1 * 32 + lane]);
        uint2 u2 = __ldg(&f2[(size_t)s2 * 32 + lane]);
        uint2 u3 = __ldg(&f2[(size_t)s3 * 32 + lane]);
        float2 a, b;
        a = unpackh2(u0.x); b = unpackh2(u0.y);
        acc.x += a.x; acc.y += a.y; acc.z += b.x; acc.w += b.y;
        a = unpackh2(u1.x); b = unpackh2(u1.y);
        acc.x += a.x; acc.y += a.y; acc.z += b.x; acc.w += b.y;
        a = unpackh2(u2.x); b = unpackh2(u2.y);
        acc.x += a.x; acc.y += a.y; acc.z += b.x; acc.w += b.y;
        a = unpackh2(u3.x); b = unpackh2(u3.y);
        acc.x += a.x; acc.y += a.y; acc.z += b.x; acc.w += b.y;
    }
    for (; i < end; ++i) {
        const int s0 = g_eadj[i];
        uint2 u0 = __ldg(&f2[(size_t)s0 * 32 + lane]);
        float2 a = unpackh2(u0.x), b = unpackh2(u0.y);
        acc.x += a.x; acc.y += a.y; acc.z += b.x; acc.w += b.y;
    }
    const float w = g_invdeg[node];
    uint2 o;
    o.x = packh2(acc.x * w, acc.y * w);
    o.y = packh2(acc.z * w, acc.w * w);
    ((uint2*)dst_feat)[(size_t)node * 32 + lane] = o;
}

// ---------------------------------------------------------------------------
// Tensor-core GEMM: out[M,128] = [A2h | m1h | xh] @ U^T + c + flag*d
// A natively fp16: stage via smem (coalesced uint4), 1 MMA per fragment pair.
// ---------------------------------------------------------------------------
__global__ __launch_bounds__(256)
void mma_gemm_kernel(float* __restrict__ out, int M) {
    extern __shared__ __half sA[];

    const int tid  = threadIdx.x;
    const int wid  = tid >> 5;
    const int lane = tid & 31;
    const int g    = lane >> 2;
    const int tq   = lane & 3;
    const int m0   = blockIdx.x * 128;
    const int moff = (wid >> 1) * 32;
    const int noff = (wid & 1) * 64;

    int   rows[4];
    bool  rowok[4];
    float flag[4];
    #pragma unroll
    for (int r = 0; r < 4; ++r) {
        const int mi = r >> 1, h = r & 1;
        rows[r]  = m0 + moff + mi * 16 + h * 8 + g;
        rowok[r] = rows[r] < M;
        flag[r]  = rowok[r] ? g_flag[rows[r]] : 0.f;
    }

    float acc[2][8][4];
    #pragma unroll
    for (int mi = 0; mi < 2; ++mi)
        #pragma unroll
        for (int ni = 0; ni < 8; ++ni)
            #pragma unroll
            for (int q = 0; q < 4; ++q) acc[mi][ni][q] = 0.f;

    #pragma unroll 1
    for (int s = 0; s < 3; ++s) {
        const __half* Asrc = (s == 0) ? g_A2h : ((s == 1) ? g_m1h : g_xh);

        if (s > 0) __syncthreads();
        // stage: 128 rows x 128 halves; each thread 8 uint4 loads -> smem
        #pragma unroll 4
        for (int idx = tid; idx < 128 * 16; idx += 256) {
            const int row = idx >> 4;
            const int c8  = (idx & 15) << 3;
            const int node = m0 + row;
            uint4 v = make_uint4(0, 0, 0, 0);
            if (node < M)
                v = *(const uint4*)(Asrc + (size_t)node * 128 + c8);
            *(uint4*)&sA[row * SA_STRIDE + c8] = v;
        }
        __syncthreads();

        #pragma unroll 1
        for (int kt = 0; kt < 8; ++kt) {
            const int kk  = kt * 16;
            const int ktg = s * 8 + kt;

            // B fragments: lane-linear coalesced global loads
            uint2 bf[8];
            #pragma unroll
            for (int ni = 0; ni < 8; ++ni) {
                const int n = noff + ni * 8 + g;
                bf[ni] = g_Upk[(ktg * 128 + n) * 4 + tq];
            }

            // A fragments: LDS (conflict-free)
            uint32_t af[2][4];
            #pragma unroll
            for (int mi = 0; mi < 2; ++mi)
                #pragma unroll
                for (int h = 0; h < 2; ++h) {
                    const int srow = moff + mi * 16 + h * 8 + g;
                    #pragma unroll
                    for (int kh = 0; kh < 2; ++kh) {
                        const int off = srow * SA_STRIDE + kk + tq * 2 + kh * 8;
                        af[mi][kh * 2 + h] = *(const uint32_t*)&sA[off];
                    }
                }

            #pragma unroll
            for (int mi = 0; mi < 2; ++mi)
                #pragma unroll
                for (int ni = 0; ni < 8; ++ni) {
                    uint32_t b2r[2] = {bf[ni].x, bf[ni].y};
                    mma16816h(acc[mi][ni], af[mi], b2r);
                }
        }
    }

    #pragma unroll
    for (int ni = 0; ni < 8; ++ni) {
        const int col = noff + ni * 8 + tq * 2;
        const float2 cc = *(const float2*)(g_c + col);
        const float2 dd = *(const float2*)(g_d + col);
        #pragma unroll
        for (int mi = 0; mi < 2; ++mi)
            #pragma unroll
            for (int h = 0; h < 2; ++h) {
                const int r = mi * 2 + h;
                if (rowok[r]) {
                    float2 o;
                    o.x = acc[mi][ni][h * 2 + 0] + cc.x + flag[r] * dd.x;
                    o.y = acc[mi][ni][h * 2 + 1] + cc.y + flag[r] * dd.y;
                    *(float2*)(out + (size_t)rows[r] * 128 + col) = o;
                }
            }
    }
}

// ---------------------------------------------------------------------------
// Launch (8 kernels)
// ---------------------------------------------------------------------------
extern "C" void kernel_launch(void* const* d_in, const int* in_sizes, int n_in,
                              void* d_out, int out_size) {
    const float* x    = (const float*)d_in[0];
    const void*  eidx = d_in[1];
    const float* W_l1 = (const float*)d_in[2];
    const float* b_l1 = (const float*)d_in[3];
    const float* W_r1 = (const float*)d_in[4];
    const float* W_l2 = (const float*)d_in[5];
    const float* b_l2 = (const float*)d_in[6];
    const float* W_r2 = (const float*)d_in[7];
    float* out = (float*)d_out;

    __half *p_xh, *p_m1h, *p_A2h;
    cudaGetSymbolAddress((void**)&p_xh,  g_xh);
    cudaGetSymbolAddress((void**)&p_m1h, g_m1h);
    cudaGetSymbolAddress((void**)&p_A2h, g_A2h);

    // 1) count + x->fp16 convert
    count_conv_kernel<<<CONV_BLOCKS, 256>>>(eidx, x);
    // 2) scanA
    scanA_kernel<<<SCAN_BLOCKS, 256>>>();
    // 3) scanB + weights
    scanB_kernel<<<1 + WEIGHT_BLOCKS, 256>>>(W_l1, W_r1, W_l2, W_r2, b_l1, b_l2);
    // 4) scanC
    scanC_kernel<<<SCAN_BLOCKS, 256>>>();
    // 5) fill
    fill_csr_kernel<<<(N_EDGES / 4 + 255) / 256, 256>>>(eidx);
    // 6-7) gathers (fp16)
    const unsigned gblocks = (N_NODES * 32 + 255) / 256;
    gather_kernel<<<gblocks, 256>>>(p_xh, p_m1h);
    gather_kernel<<<gblocks, 256>>>(p_m1h, p_A2h);
    // 8) fused tensor-core GEMM
    mma_gemm_kernel<<<(N_NODES + 127) / 128, 256, SMEM_BYTES>>>(out, N_NODES);
}